// round 1
// baseline (speedup 1.0000x reference)
#include <cuda_runtime.h>
#include <math.h>

#define S_TOK 8192
#define HID   1024
#define INTR  4096
#define NE    8
#define CAP   1024

// ---- scratch (device globals: no allocation allowed) ----
__device__ float g_attn[S_TOK * HID];        // layernorm output
__device__ float g_disp[NE * CAP * HID];     // dispatched tokens
__device__ float g_h[NE * CAP * INTR];       // expert hidden
__device__ float g_eo[NE * CAP * HID];       // expert output
__device__ float g_rh[S_TOK * INTR];         // residual-MLP hidden
__device__ float g_rmlp[S_TOK * HID];        // residual-MLP output
__device__ int   g_expidx[S_TOK];
__device__ int   g_dest[S_TOK];              // e*CAP+c or -1 (dropped)
__device__ int   g_tos[NE * CAP];            // token of slot, -1 if empty
__device__ float g_gate[S_TOK];
__device__ float g_coef0[S_TOK];
__device__ float g_coef1[S_TOK];

__device__ __forceinline__ float gelu_tanh(float x) {
    float x3 = x * x * x;
    return 0.5f * x * (1.f + tanhf(0.7978845608028654f * (x + 0.044715f * x3)));
}

// ===========================================================================
// LayerNorm + gate logits (8 experts) + residual coef logits (2), fused.
// One block (320 threads = 10 warps) per token: warps 0-7 -> expert dots,
// warps 8-9 -> res_coef dots.
// ===========================================================================
__global__ void ln_gate_kernel(const float* __restrict__ x,
                               const float* __restrict__ nw,
                               const float* __restrict__ nb,
                               const float* __restrict__ wg,
                               const float* __restrict__ res_coef) {
    __shared__ float row[HID];
    __shared__ float rs[10], rq[10];
    __shared__ float dots[10];
    __shared__ float s_mean, s_rstd;

    const int s = blockIdx.x;
    const int tid = threadIdx.x;
    const int lane = tid & 31;
    const int w = tid >> 5;   // warp id 0..9

    const float* xr = x + (size_t)s * HID;
    float sum = 0.f, sq = 0.f;
    for (int i = tid; i < HID; i += 320) {
        float v = xr[i];
        row[i] = v;
        sum += v; sq += v * v;
    }
    #pragma unroll
    for (int o = 16; o > 0; o >>= 1) {
        sum += __shfl_down_sync(0xffffffffu, sum, o);
        sq  += __shfl_down_sync(0xffffffffu, sq,  o);
    }
    if (lane == 0) { rs[w] = sum; rq[w] = sq; }
    __syncthreads();
    if (tid == 0) {
        float ts = 0.f, tq = 0.f;
        #pragma unroll
        for (int i = 0; i < 10; i++) { ts += rs[i]; tq += rq[i]; }
        float mean = ts * (1.f / HID);
        float var  = tq * (1.f / HID) - mean * mean;
        s_mean = mean;
        s_rstd = rsqrtf(var + 1e-12f);
    }
    __syncthreads();
    const float mean = s_mean, rstd = s_rstd;
    float* outr = g_attn + (size_t)s * HID;
    for (int i = tid; i < HID; i += 320) {
        float v = (row[i] - mean) * rstd * nw[i] + nb[i];
        row[i] = v;
        outr[i] = v;
    }
    __syncthreads();

    // dots
    float d = 0.f;
    if (w < 8) {
        for (int m = lane; m < HID; m += 32) d += row[m] * wg[m * NE + w];
    } else {
        int c = w - 8;
        for (int m = lane; m < HID; m += 32) d += row[m] * res_coef[m * 2 + c];
    }
    #pragma unroll
    for (int o = 16; o > 0; o >>= 1) d += __shfl_down_sync(0xffffffffu, d, o);
    if (lane == 0) dots[w] = d;
    __syncthreads();

    if (tid == 0) {
        float mx = dots[0]; int am = 0;
        #pragma unroll
        for (int e = 1; e < 8; e++) if (dots[e] > mx) { mx = dots[e]; am = e; }
        float se = 0.f;
        #pragma unroll
        for (int e = 0; e < 8; e++) se += expf(dots[e] - mx);
        g_expidx[s] = am;
        g_gate[s] = 1.f / se;       // exp(mx - mx) / se
        float a = dots[8], b = dots[9];
        float m2 = fmaxf(a, b);
        float ea = expf(a - m2), eb = expf(b - m2);
        float inv = 1.f / (ea + eb);
        g_coef0[s] = ea * inv;
        g_coef1[s] = eb * inv;
    }
}

// ===========================================================================
// Capacity scan: single block, warp e scans all tokens for expert e and
// assigns slots via exclusive cumsum (warp ballot prefix).
// ===========================================================================
__global__ void scan_kernel() {
    const int tid = threadIdx.x;
    for (int i = tid; i < NE * CAP; i += 256) g_tos[i] = -1;
    __syncthreads();
    const int lane = tid & 31;
    const int e = tid >> 5;  // expert 0..7
    int count = 0;
    for (int base = 0; base < S_TOK; base += 32) {
        int s = base + lane;
        bool sel = (g_expidx[s] == e);
        unsigned mask = __ballot_sync(0xffffffffu, sel);
        if (sel) {
            int c = count + __popc(mask & ((1u << lane) - 1u));
            if (c < CAP) {
                g_dest[s] = e * CAP + c;
                g_tos[e * CAP + c] = s;
            } else {
                g_dest[s] = -1;
            }
        }
        count += __popc(mask);
    }
}

// ===========================================================================
// Dispatch scatter: one block per (expert, slot)
// ===========================================================================
__global__ void dispatch_kernel() {
    const int slot = blockIdx.x;
    const int tid = threadIdx.x;
    const int t = g_tos[slot];
    float4* dst = (float4*)(g_disp + (size_t)slot * HID);
    if (t >= 0) {
        const float4* src = (const float4*)(g_attn + (size_t)t * HID);
        dst[tid] = src[tid];
    } else {
        dst[tid] = make_float4(0.f, 0.f, 0.f, 0.f);
    }
}

// ===========================================================================
// Tiled SGEMM: C[bz] = act(A[bz] @ B[bz] + bias[bz])
// BM=BN=128, BK=16, 256 threads, 8x8 per thread. Dims multiples of 128.
// Batch strides implied: A += bz*M*K, B += bz*K*N, bias += bz*N, C += bz*M*N.
// ===========================================================================
template <int ACT>
__global__ __launch_bounds__(256) void gemm_kernel(
    const float* __restrict__ A, const float* __restrict__ B,
    const float* __restrict__ bias, float* __restrict__ C,
    int M, int N, int K) {
    const int BM = 128, BN = 128, BK = 16;
    __shared__ float As[BK][BM + 4];   // transposed A tile, padded
    __shared__ float Bs[BK][BN];

    const int tid = threadIdx.x;
    const long bz = blockIdx.z;
    A    += bz * (long)M * K + (long)blockIdx.y * BM * K;
    B    += bz * (long)K * N + blockIdx.x * BN;
    C    += bz * (long)M * N + (long)blockIdx.y * BM * N + blockIdx.x * BN;
    bias += bz * (long)N + blockIdx.x * BN;

    // A-tile load mapping: row = tid/2, 8 consecutive cols per thread
    const int ar = tid >> 1;
    const int ac = (tid & 1) * 8;
    // B-tile load mapping: row = tid/32 (and +8), 1 float4 per thread per row
    const int br = tid >> 5;
    const int bc = (tid & 31) * 4;

    const int tx = tid & 15;   // N micro-tile
    const int ty = tid >> 4;   // M micro-tile

    float acc[8][8] = {};

    for (int kt = 0; kt < K; kt += BK) {
        float4 a0 = *(const float4*)(A + (long)ar * K + kt + ac);
        float4 a1 = *(const float4*)(A + (long)ar * K + kt + ac + 4);
        As[ac + 0][ar] = a0.x; As[ac + 1][ar] = a0.y;
        As[ac + 2][ar] = a0.z; As[ac + 3][ar] = a0.w;
        As[ac + 4][ar] = a1.x; As[ac + 5][ar] = a1.y;
        As[ac + 6][ar] = a1.z; As[ac + 7][ar] = a1.w;
        *(float4*)(&Bs[br][bc])     = *(const float4*)(B + (long)(kt + br) * N + bc);
        *(float4*)(&Bs[br + 8][bc]) = *(const float4*)(B + (long)(kt + br + 8) * N + bc);
        __syncthreads();

        #pragma unroll
        for (int k = 0; k < BK; k++) {
            float a[8], b[8];
            *(float4*)(a)     = *(const float4*)(&As[k][ty * 8]);
            *(float4*)(a + 4) = *(const float4*)(&As[k][ty * 8 + 4]);
            *(float4*)(b)     = *(const float4*)(&Bs[k][tx * 8]);
            *(float4*)(b + 4) = *(const float4*)(&Bs[k][tx * 8 + 4]);
            #pragma unroll
            for (int i = 0; i < 8; i++)
                #pragma unroll
                for (int j = 0; j < 8; j++)
                    acc[i][j] += a[i] * b[j];
        }
        __syncthreads();
    }

    float bv[8];
    *(float4*)(bv)     = *(const float4*)(bias + tx * 8);
    *(float4*)(bv + 4) = *(const float4*)(bias + tx * 8 + 4);
    #pragma unroll
    for (int i = 0; i < 8; i++) {
        float v[8];
        #pragma unroll
        for (int j = 0; j < 8; j++) {
            float t = acc[i][j] + bv[j];
            v[j] = ACT ? gelu_tanh(t) : t;
        }
        float* crow = C + (long)(ty * 8 + i) * N + tx * 8;
        *(float4*)(crow)     = *(const float4*)(v);
        *(float4*)(crow + 4) = *(const float4*)(v + 4);
    }
}

// ===========================================================================
// Final combine: out = x + coef0*res_mlp + coef1*gate*expert_out
// ===========================================================================
__global__ void combine_kernel(const float* __restrict__ x, float* __restrict__ out) {
    const int s = blockIdx.x;
    const int tid = threadIdx.x;
    const int d = g_dest[s];
    const float c0 = g_coef0[s];
    const float c1g = g_coef1[s] * g_gate[s];

    float4 xv = ((const float4*)(x + (size_t)s * HID))[tid];
    float4 rv = ((const float4*)(g_rmlp + (size_t)s * HID))[tid];
    float4 ev = (d >= 0) ? ((const float4*)(g_eo + (size_t)d * HID))[tid]
                         : make_float4(0.f, 0.f, 0.f, 0.f);
    float4 o;
    o.x = xv.x + c0 * rv.x + c1g * ev.x;
    o.y = xv.y + c0 * rv.y + c1g * ev.y;
    o.z = xv.z + c0 * rv.z + c1g * ev.z;
    o.w = xv.w + c0 * rv.w + c1g * ev.w;
    ((float4*)(out + (size_t)s * HID))[tid] = o;
}

// ===========================================================================
extern "C" void kernel_launch(void* const* d_in, const int* in_sizes, int n_in,
                              void* d_out, int out_size) {
    const float* x       = (const float*)d_in[0];
    const float* attn_nw = (const float*)d_in[1];
    const float* attn_nb = (const float*)d_in[2];
    const float* wg      = (const float*)d_in[3];
    const float* inter_w = (const float*)d_in[4];
    const float* inter_b = (const float*)d_in[5];
    const float* out_w   = (const float*)d_in[6];
    const float* out_b   = (const float*)d_in[7];
    const float* ri_w    = (const float*)d_in[8];
    const float* ri_b    = (const float*)d_in[9];
    const float* ro_w    = (const float*)d_in[10];
    const float* ro_b    = (const float*)d_in[11];
    const float* rcoef   = (const float*)d_in[12];
    float* out = (float*)d_out;

    void *p_attn, *p_disp, *p_h, *p_eo, *p_rh, *p_rmlp;
    cudaGetSymbolAddress(&p_attn, g_attn);
    cudaGetSymbolAddress(&p_disp, g_disp);
    cudaGetSymbolAddress(&p_h,    g_h);
    cudaGetSymbolAddress(&p_eo,   g_eo);
    cudaGetSymbolAddress(&p_rh,   g_rh);
    cudaGetSymbolAddress(&p_rmlp, g_rmlp);

    // 1. LayerNorm + gating logits + coef
    ln_gate_kernel<<<S_TOK, 320>>>(x, attn_nw, attn_nb, wg, rcoef);
    // 2. capacity scan
    scan_kernel<<<1, 256>>>();
    // 3. dispatch scatter
    dispatch_kernel<<<NE * CAP, 256>>>();
    // 4. expert GEMM1 + GELU: [1024,1024]@[1024,4096] x8
    gemm_kernel<1><<<dim3(INTR / 128, CAP / 128, NE), 256>>>(
        (const float*)p_disp, inter_w, inter_b, (float*)p_h, CAP, INTR, HID);
    // 5. expert GEMM2: [1024,4096]@[4096,1024] x8
    gemm_kernel<0><<<dim3(HID / 128, CAP / 128, NE), 256>>>(
        (const float*)p_h, out_w, out_b, (float*)p_eo, CAP, HID, INTR);
    // 6. residual GEMM1 + GELU: [8192,1024]@[1024,4096]
    gemm_kernel<1><<<dim3(INTR / 128, S_TOK / 128, 1), 256>>>(
        (const float*)p_attn, ri_w, ri_b, (float*)p_rh, S_TOK, INTR, HID);
    // 7. residual GEMM2: [8192,4096]@[4096,1024]
    gemm_kernel<0><<<dim3(HID / 128, S_TOK / 128, 1), 256>>>(
        (const float*)p_rh, ro_w, ro_b, (float*)p_rmlp, S_TOK, HID, INTR);
    // 8. combine
    combine_kernel<<<S_TOK, 256>>>(x, out);
}

// round 3
// speedup vs baseline: 2.9931x; 2.9931x over previous
#include <cuda_runtime.h>
#include <cuda_bf16.h>
#include <cstdint>
#include <math.h>

#define S_TOK 8192
#define HID   1024
#define INTR  4096
#define NE    8
#define CAP   1024

#define BM 128
#define BN 128
#define BK 64               // bf16 elements per k-tile (128 bytes/row)
#define STAGE_BYTES 65536   // 4 tensors x 128 rows x 128B
#define SMEM_BYTES  (2 * STAGE_BYTES)

// ---------------- device scratch (no allocation allowed) ----------------
__device__ __nv_bfloat16 g_attn_h[S_TOK * HID];
__device__ __nv_bfloat16 g_attn_l[S_TOK * HID];
__device__ __nv_bfloat16 g_disp_h[NE * CAP * HID];
__device__ __nv_bfloat16 g_disp_l[NE * CAP * HID];
__device__ __nv_bfloat16 g_h_h[NE * CAP * INTR];
__device__ __nv_bfloat16 g_h_l[NE * CAP * INTR];
__device__ float         g_eo[NE * CAP * HID];
__device__ __nv_bfloat16 g_rh_h[S_TOK * INTR];
__device__ __nv_bfloat16 g_rh_l[S_TOK * INTR];
__device__ float         g_rmlp[S_TOK * HID];
__device__ __nv_bfloat16 g_iwT_h[NE * INTR * HID];  // [e][N=INTR][K=HID]
__device__ __nv_bfloat16 g_iwT_l[NE * INTR * HID];
__device__ __nv_bfloat16 g_owT_h[NE * HID * INTR];  // [e][N=HID][K=INTR]
__device__ __nv_bfloat16 g_owT_l[NE * HID * INTR];
__device__ __nv_bfloat16 g_riT_h[INTR * HID];
__device__ __nv_bfloat16 g_riT_l[INTR * HID];
__device__ __nv_bfloat16 g_roT_h[HID * INTR];
__device__ __nv_bfloat16 g_roT_l[HID * INTR];
__device__ int   g_expidx[S_TOK];
__device__ int   g_dest[S_TOK];
__device__ int   g_tos[NE * CAP];
__device__ float g_gate[S_TOK];
__device__ float g_coef0[S_TOK];
__device__ float g_coef1[S_TOK];

// ---------------- helpers ----------------
__device__ __forceinline__ float gelu_tanh(float x) {
    float x3 = x * x * x;
    return 0.5f * x * (1.f + tanhf(0.7978845608028654f * (x + 0.044715f * x3)));
}

__device__ __forceinline__ uint32_t smem_u32(const void* p) {
    uint32_t a;
    asm("{ .reg .u64 t; cvta.to.shared.u64 t, %1; cvt.u32.u64 %0, t; }" : "=r"(a) : "l"(p));
    return a;
}

__device__ __forceinline__ void ldsm_x4(uint32_t (&r)[4], uint32_t addr) {
    asm volatile("ldmatrix.sync.aligned.m8n8.x4.shared.b16 {%0,%1,%2,%3}, [%4];"
                 : "=r"(r[0]), "=r"(r[1]), "=r"(r[2]), "=r"(r[3]) : "r"(addr));
}

__device__ __forceinline__ void mma16816(float (&c)[4], const uint32_t (&a)[4],
                                         const uint32_t* b) {
    asm volatile(
        "mma.sync.aligned.m16n8k16.row.col.f32.bf16.bf16.f32 "
        "{%0,%1,%2,%3}, {%4,%5,%6,%7}, {%8,%9}, {%0,%1,%2,%3};"
        : "+f"(c[0]), "+f"(c[1]), "+f"(c[2]), "+f"(c[3])
        : "r"(a[0]), "r"(a[1]), "r"(a[2]), "r"(a[3]), "r"(b[0]), "r"(b[1]));
}

#define CP_ASYNC16(sm, gm) asm volatile("cp.async.cg.shared.global [%0], [%1], 16;" :: "r"(sm), "l"(gm))
#define CP_COMMIT()        asm volatile("cp.async.commit_group;" ::: "memory")
#define CP_WAIT(n)         asm volatile("cp.async.wait_group %0;" :: "n"(n) : "memory")

__device__ __forceinline__ void split_bf16(float v, __nv_bfloat16& h, __nv_bfloat16& l) {
    h = __float2bfloat16(v);
    l = __float2bfloat16(v - __bfloat162float(h));
}

// ===========================================================================
// LayerNorm + gate logits + res_coef; emits attn as bf16 hi/lo
// ===========================================================================
__global__ void ln_gate_kernel(const float* __restrict__ x,
                               const float* __restrict__ nw,
                               const float* __restrict__ nb,
                               const float* __restrict__ wg,
                               const float* __restrict__ res_coef) {
    __shared__ float row[HID];
    __shared__ float rs[10], rq[10];
    __shared__ float dots[10];
    __shared__ float s_mean, s_rstd;

    const int s = blockIdx.x;
    const int tid = threadIdx.x;
    const int lane = tid & 31;
    const int w = tid >> 5;

    const float* xr = x + (size_t)s * HID;
    float sum = 0.f, sq = 0.f;
    for (int i = tid; i < HID; i += 320) {
        float v = xr[i];
        row[i] = v;
        sum += v; sq += v * v;
    }
    #pragma unroll
    for (int o = 16; o > 0; o >>= 1) {
        sum += __shfl_down_sync(0xffffffffu, sum, o);
        sq  += __shfl_down_sync(0xffffffffu, sq,  o);
    }
    if (lane == 0) { rs[w] = sum; rq[w] = sq; }
    __syncthreads();
    if (tid == 0) {
        float ts = 0.f, tq = 0.f;
        #pragma unroll
        for (int i = 0; i < 10; i++) { ts += rs[i]; tq += rq[i]; }
        float mean = ts * (1.f / HID);
        float var  = tq * (1.f / HID) - mean * mean;
        s_mean = mean;
        s_rstd = rsqrtf(var + 1e-12f);
    }
    __syncthreads();
    const float mean = s_mean, rstd = s_rstd;
    for (int i = tid; i < HID; i += 320) {
        float v = (row[i] - mean) * rstd * nw[i] + nb[i];
        row[i] = v;
        __nv_bfloat16 h, l;
        split_bf16(v, h, l);
        g_attn_h[(size_t)s * HID + i] = h;
        g_attn_l[(size_t)s * HID + i] = l;
    }
    __syncthreads();

    float d = 0.f;
    if (w < 8) {
        for (int m = lane; m < HID; m += 32) d += row[m] * wg[m * NE + w];
    } else {
        int c = w - 8;
        for (int m = lane; m < HID; m += 32) d += row[m] * res_coef[m * 2 + c];
    }
    #pragma unroll
    for (int o = 16; o > 0; o >>= 1) d += __shfl_down_sync(0xffffffffu, d, o);
    if (lane == 0) dots[w] = d;
    __syncthreads();

    if (tid == 0) {
        float mx = dots[0]; int am = 0;
        #pragma unroll
        for (int e = 1; e < 8; e++) if (dots[e] > mx) { mx = dots[e]; am = e; }
        float se = 0.f;
        #pragma unroll
        for (int e = 0; e < 8; e++) se += expf(dots[e] - mx);
        g_expidx[s] = am;
        g_gate[s] = 1.f / se;
        float a = dots[8], b = dots[9];
        float m2 = fmaxf(a, b);
        float ea = expf(a - m2), eb = expf(b - m2);
        float inv = 1.f / (ea + eb);
        g_coef0[s] = ea * inv;
        g_coef1[s] = eb * inv;
    }
}

// ===========================================================================
__global__ void scan_kernel() {
    const int tid = threadIdx.x;
    for (int i = tid; i < NE * CAP; i += 256) g_tos[i] = -1;
    __syncthreads();
    const int lane = tid & 31;
    const int e = tid >> 5;
    int count = 0;
    for (int base = 0; base < S_TOK; base += 32) {
        int s = base + lane;
        bool sel = (g_expidx[s] == e);
        unsigned mask = __ballot_sync(0xffffffffu, sel);
        if (sel) {
            int c = count + __popc(mask & ((1u << lane) - 1u));
            if (c < CAP) {
                g_dest[s] = e * CAP + c;
                g_tos[e * CAP + c] = s;
            } else {
                g_dest[s] = -1;
            }
        }
        count += __popc(mask);
    }
}

// ===========================================================================
__global__ void dispatch_kernel() {
    const int slot = blockIdx.x;
    const int tid = threadIdx.x;
    const int t = g_tos[slot];
    uint2* dh = (uint2*)(g_disp_h + (size_t)slot * HID);
    uint2* dl = (uint2*)(g_disp_l + (size_t)slot * HID);
    if (t >= 0) {
        dh[tid] = ((const uint2*)(g_attn_h + (size_t)t * HID))[tid];
        dl[tid] = ((const uint2*)(g_attn_l + (size_t)t * HID))[tid];
    } else {
        dh[tid] = make_uint2(0u, 0u);
        dl[tid] = make_uint2(0u, 0u);
    }
}

// ===========================================================================
// Weight transpose + hi/lo split: W [K,N] fp32 -> Th/Tl [N,K] bf16
// ===========================================================================
__global__ void wconv_kernel(const float* __restrict__ W,
                             __nv_bfloat16* __restrict__ Th,
                             __nv_bfloat16* __restrict__ Tl,
                             int K, int N) {
    __shared__ float tile[32][33];
    const int n0 = blockIdx.x * 32;
    const int k0 = blockIdx.y * 32;
    const long zb = blockIdx.z;
    W  += zb * (long)K * N;
    Th += zb * (long)K * N;
    Tl += zb * (long)K * N;
    const int tx = threadIdx.x, ty = threadIdx.y;
    #pragma unroll
    for (int j = 0; j < 4; j++) {
        int r = ty + j * 8;
        tile[r][tx] = W[(size_t)(k0 + r) * N + n0 + tx];
    }
    __syncthreads();
    #pragma unroll
    for (int j = 0; j < 4; j++) {
        int r = ty + j * 8;
        float v = tile[tx][r];
        __nv_bfloat16 h, l;
        split_bf16(v, h, l);
        size_t o = (size_t)(n0 + r) * K + k0 + tx;
        Th[o] = h;
        Tl[o] = l;
    }
}

// ===========================================================================
// mma.sync split-bf16 GEMM: C = act(Ahl @ Bhl^T + bias)
// A: [M,K] K-major hi/lo bf16. B: [N,K] K-major hi/lo bf16.
// BM=BN=128, BK=64, 256 threads (8 warps, 2m x 4n), warp tile 64x32.
// 2-stage cp.async pipeline, SW128-style xor swizzle (128B rows).
// ACT=1: gelu, emit bf16 hi/lo. ACT=0: emit fp32.
// ===========================================================================
template <int ACT>
__global__ __launch_bounds__(256, 1)
void mma_gemm(const __nv_bfloat16* __restrict__ Ah, const __nv_bfloat16* __restrict__ Al,
              const __nv_bfloat16* __restrict__ Bh, const __nv_bfloat16* __restrict__ Bl,
              const float* __restrict__ bias,
              float* __restrict__ Cf,
              __nv_bfloat16* __restrict__ Ch, __nv_bfloat16* __restrict__ Cl,
              int M, int N, int K) {
    extern __shared__ char smem[];
    const uint32_t sbase = smem_u32(smem);
    const int tid = threadIdx.x;
    const int lane = tid & 31;
    const int wid = tid >> 5;
    const int wm = wid >> 2;          // 0..1 -> warp row (64 rows each)
    const int wn = wid & 3;           // 0..3 -> warp col (32 cols each)
    const long bz = blockIdx.z;
    const int m0 = blockIdx.y * BM;
    const int n0 = blockIdx.x * BN;

    const __nv_bfloat16* srcs[4] = {
        Ah + bz * (long)M * K + (size_t)m0 * K,
        Al + bz * (long)M * K + (size_t)m0 * K,
        Bh + bz * (long)N * K + (size_t)n0 * K,
        Bl + bz * (long)N * K + (size_t)n0 * K
    };
    bias += bz * (long)N;

    // per-thread load pattern: 4 chunks per tensor per stage
    const int lrow0 = tid >> 3;        // rows tid/8 + 32*i
    const int lch   = tid & 7;         // 16B chunk within 128B row

    float acc[4][4][4];
    #pragma unroll
    for (int a = 0; a < 4; a++)
        #pragma unroll
        for (int b = 0; b < 4; b++)
            #pragma unroll
            for (int c = 0; c < 4; c++) acc[a][b][c] = 0.f;

    const int NT = K / BK;

    // ---- loader ----
    auto load_stage = [&](int st, int kt) {
        const uint32_t stb = sbase + (uint32_t)st * STAGE_BYTES;
        #pragma unroll
        for (int t = 0; t < 4; t++) {
            const __nv_bfloat16* g = srcs[t] + kt + lch * 8;
            const uint32_t tb = stb + (uint32_t)t * 16384u;
            #pragma unroll
            for (int i = 0; i < 4; i++) {
                int row = lrow0 + i * 32;
                uint32_t sm = tb + (uint32_t)(row * 128 + ((lch ^ (row & 7)) << 4));
                CP_ASYNC16(sm, g + (size_t)row * K);
            }
        }
    };

    load_stage(0, 0);
    CP_COMMIT();

    for (int s = 0; s < NT; s++) {
        if (s + 1 < NT) {
            load_stage((s + 1) & 1, (s + 1) * BK);
            CP_COMMIT();
            CP_WAIT(1);
        } else {
            CP_WAIT(0);
        }
        __syncthreads();

        const uint32_t stb = sbase + (uint32_t)(s & 1) * STAGE_BYTES;
        const uint32_t Ahb = stb, Alb = stb + 16384u, Bhb = stb + 32768u, Blb = stb + 49152u;

        const int g = lane >> 3;       // ldmatrix address group
        const int li = lane & 7;

        #pragma unroll
        for (int kk = 0; kk < 4; kk++) {
            // A fragments: groups (m0-7,k0),(m8-15,k0),(m0-7,k8),(m8-15,k8)
            uint32_t ah[4][4], al[4][4];
            {
                const int arow_b = wm * 64 + (g & 1) * 8 + li;
                const int ach = kk * 2 + (g >> 1);
                #pragma unroll
                for (int mf = 0; mf < 4; mf++) {
                    int r = arow_b + mf * 16;
                    uint32_t off = (uint32_t)(r * 128 + ((ach ^ (r & 7)) << 4));
                    ldsm_x4(ah[mf], Ahb + off);
                    ldsm_x4(al[mf], Alb + off);
                }
            }
            // B fragments: groups (n0-7,k0),(n0-7,k8),(n8-15,k0),(n8-15,k8)
            uint32_t bh[4][2], bl[4][2];
            {
                const int brow_b = wn * 32 + (g >> 1) * 8 + li;
                const int bch = kk * 2 + (g & 1);
                #pragma unroll
                for (int nb = 0; nb < 2; nb++) {
                    int r = brow_b + nb * 16;
                    uint32_t off = (uint32_t)(r * 128 + ((bch ^ (r & 7)) << 4));
                    uint32_t t4[4];
                    ldsm_x4(t4, Bhb + off);
                    bh[nb * 2][0] = t4[0]; bh[nb * 2][1] = t4[1];
                    bh[nb * 2 + 1][0] = t4[2]; bh[nb * 2 + 1][1] = t4[3];
                    ldsm_x4(t4, Blb + off);
                    bl[nb * 2][0] = t4[0]; bl[nb * 2][1] = t4[1];
                    bl[nb * 2 + 1][0] = t4[2]; bl[nb * 2 + 1][1] = t4[3];
                }
            }
            #pragma unroll
            for (int mf = 0; mf < 4; mf++)
                #pragma unroll
                for (int nf = 0; nf < 4; nf++) {
                    mma16816(acc[mf][nf], ah[mf], bh[nf]);
                    mma16816(acc[mf][nf], ah[mf], bl[nf]);
                    mma16816(acc[mf][nf], al[mf], bh[nf]);
                }
        }
        __syncthreads();
    }

    // ---- epilogue ----
    const int mrow = m0 + wm * 64 + (lane >> 2);
    const int ncol0 = n0 + wn * 32 + (lane & 3) * 2;
    #pragma unroll
    for (int nf = 0; nf < 4; nf++) {
        const int n = ncol0 + nf * 8;
        const float bv0 = bias[n], bv1 = bias[n + 1];
        #pragma unroll
        for (int mf = 0; mf < 4; mf++) {
            const float* c = acc[mf][nf];
            const int m_a = mrow + mf * 16;
            const int m_b = m_a + 8;
            if (ACT) {
                float v00 = gelu_tanh(c[0] + bv0), v01 = gelu_tanh(c[1] + bv1);
                float v10 = gelu_tanh(c[2] + bv0), v11 = gelu_tanh(c[3] + bv1);
                __nv_bfloat16 h0, l0, h1, l1;
                split_bf16(v00, h0, l0); split_bf16(v01, h1, l1);
                uint32_t ph = (uint32_t)__bfloat16_as_ushort(h0) |
                              ((uint32_t)__bfloat16_as_ushort(h1) << 16);
                uint32_t pl = (uint32_t)__bfloat16_as_ushort(l0) |
                              ((uint32_t)__bfloat16_as_ushort(l1) << 16);
                *(uint32_t*)(Ch + bz * (long)M * N + (size_t)m_a * N + n) = ph;
                *(uint32_t*)(Cl + bz * (long)M * N + (size_t)m_a * N + n) = pl;
                split_bf16(v10, h0, l0); split_bf16(v11, h1, l1);
                ph = (uint32_t)__bfloat16_as_ushort(h0) |
                     ((uint32_t)__bfloat16_as_ushort(h1) << 16);
                pl = (uint32_t)__bfloat16_as_ushort(l0) |
                     ((uint32_t)__bfloat16_as_ushort(l1) << 16);
                *(uint32_t*)(Ch + bz * (long)M * N + (size_t)m_b * N + n) = ph;
                *(uint32_t*)(Cl + bz * (long)M * N + (size_t)m_b * N + n) = pl;
            } else {
                float2 r0 = make_float2(c[0] + bv0, c[1] + bv1);
                float2 r1 = make_float2(c[2] + bv0, c[3] + bv1);
                *(float2*)(Cf + bz * (long)M * N + (size_t)m_a * N + n) = r0;
                *(float2*)(Cf + bz * (long)M * N + (size_t)m_b * N + n) = r1;
            }
        }
    }
}

// ===========================================================================
__global__ void combine_kernel(const float* __restrict__ x, float* __restrict__ out) {
    const int s = blockIdx.x;
    const int tid = threadIdx.x;
    const int d = g_dest[s];
    const float c0 = g_coef0[s];
    const float c1g = g_coef1[s] * g_gate[s];

    float4 xv = ((const float4*)(x + (size_t)s * HID))[tid];
    float4 rv = ((const float4*)(g_rmlp + (size_t)s * HID))[tid];
    float4 ev = (d >= 0) ? ((const float4*)(g_eo + (size_t)d * HID))[tid]
                         : make_float4(0.f, 0.f, 0.f, 0.f);
    float4 o;
    o.x = xv.x + c0 * rv.x + c1g * ev.x;
    o.y = xv.y + c0 * rv.y + c1g * ev.y;
    o.z = xv.z + c0 * rv.z + c1g * ev.z;
    o.w = xv.w + c0 * rv.w + c1g * ev.w;
    ((float4*)(out + (size_t)s * HID))[tid] = o;
}

// ===========================================================================
extern "C" void kernel_launch(void* const* d_in, const int* in_sizes, int n_in,
                              void* d_out, int out_size) {
    const float* x       = (const float*)d_in[0];
    const float* attn_nw = (const float*)d_in[1];
    const float* attn_nb = (const float*)d_in[2];
    const float* wg      = (const float*)d_in[3];
    const float* inter_w = (const float*)d_in[4];
    const float* inter_b = (const float*)d_in[5];
    const float* out_w   = (const float*)d_in[6];
    const float* out_b   = (const float*)d_in[7];
    const float* ri_w    = (const float*)d_in[8];
    const float* ri_b    = (const float*)d_in[9];
    const float* ro_w    = (const float*)d_in[10];
    const float* ro_b    = (const float*)d_in[11];
    const float* rcoef   = (const float*)d_in[12];
    float* out = (float*)d_out;

    cudaFuncSetAttribute(mma_gemm<0>, cudaFuncAttributeMaxDynamicSharedMemorySize, SMEM_BYTES);
    cudaFuncSetAttribute(mma_gemm<1>, cudaFuncAttributeMaxDynamicSharedMemorySize, SMEM_BYTES);

    void *p_disp_h, *p_disp_l, *p_h_h, *p_h_l, *p_eo, *p_attn_h, *p_attn_l;
    void *p_rh_h, *p_rh_l, *p_rmlp;
    void *p_iwT_h, *p_iwT_l, *p_owT_h, *p_owT_l, *p_riT_h, *p_riT_l, *p_roT_h, *p_roT_l;
    cudaGetSymbolAddress(&p_disp_h, g_disp_h);
    cudaGetSymbolAddress(&p_disp_l, g_disp_l);
    cudaGetSymbolAddress(&p_h_h, g_h_h);
    cudaGetSymbolAddress(&p_h_l, g_h_l);
    cudaGetSymbolAddress(&p_eo, g_eo);
    cudaGetSymbolAddress(&p_attn_h, g_attn_h);
    cudaGetSymbolAddress(&p_attn_l, g_attn_l);
    cudaGetSymbolAddress(&p_rh_h, g_rh_h);
    cudaGetSymbolAddress(&p_rh_l, g_rh_l);
    cudaGetSymbolAddress(&p_rmlp, g_rmlp);
    cudaGetSymbolAddress(&p_iwT_h, g_iwT_h);
    cudaGetSymbolAddress(&p_iwT_l, g_iwT_l);
    cudaGetSymbolAddress(&p_owT_h, g_owT_h);
    cudaGetSymbolAddress(&p_owT_l, g_owT_l);
    cudaGetSymbolAddress(&p_riT_h, g_riT_h);
    cudaGetSymbolAddress(&p_riT_l, g_riT_l);
    cudaGetSymbolAddress(&p_roT_h, g_roT_h);
    cudaGetSymbolAddress(&p_roT_l, g_roT_l);

    dim3 wb(32, 8);
    wconv_kernel<<<dim3(INTR / 32, HID / 32, NE), wb>>>(
        inter_w, (__nv_bfloat16*)p_iwT_h, (__nv_bfloat16*)p_iwT_l, HID, INTR);
    wconv_kernel<<<dim3(HID / 32, INTR / 32, NE), wb>>>(
        out_w, (__nv_bfloat16*)p_owT_h, (__nv_bfloat16*)p_owT_l, INTR, HID);
    wconv_kernel<<<dim3(INTR / 32, HID / 32, 1), wb>>>(
        ri_w, (__nv_bfloat16*)p_riT_h, (__nv_bfloat16*)p_riT_l, HID, INTR);
    wconv_kernel<<<dim3(HID / 32, INTR / 32, 1), wb>>>(
        ro_w, (__nv_bfloat16*)p_roT_h, (__nv_bfloat16*)p_roT_l, INTR, HID);

    ln_gate_kernel<<<S_TOK, 320>>>(x, attn_nw, attn_nb, wg, rcoef);
    scan_kernel<<<1, 256>>>();
    dispatch_kernel<<<NE * CAP, 256>>>();

    // expert GEMM1 + GELU: [1024,1024]@[1024,4096] x8 -> h (bf16 hi/lo)
    mma_gemm<1><<<dim3(INTR / BN, CAP / BM, NE), 256, SMEM_BYTES>>>(
        (const __nv_bfloat16*)p_disp_h, (const __nv_bfloat16*)p_disp_l,
        (const __nv_bfloat16*)p_iwT_h, (const __nv_bfloat16*)p_iwT_l,
        inter_b, nullptr, (__nv_bfloat16*)p_h_h, (__nv_bfloat16*)p_h_l,
        CAP, INTR, HID);
    // expert GEMM2: [1024,4096]@[4096,1024] x8 -> eo (fp32)
    mma_gemm<0><<<dim3(HID / BN, CAP / BM, NE), 256, SMEM_BYTES>>>(
        (const __nv_bfloat16*)p_h_h, (const __nv_bfloat16*)p_h_l,
        (const __nv_bfloat16*)p_owT_h, (const __nv_bfloat16*)p_owT_l,
        out_b, (float*)p_eo, nullptr, nullptr,
        CAP, HID, INTR);
    // res GEMM1 + GELU: [8192,1024]@[1024,4096] -> rh (bf16 hi/lo)
    mma_gemm<1><<<dim3(INTR / BN, S_TOK / BM, 1), 256, SMEM_BYTES>>>(
        (const __nv_bfloat16*)p_attn_h, (const __nv_bfloat16*)p_attn_l,
        (const __nv_bfloat16*)p_riT_h, (const __nv_bfloat16*)p_riT_l,
        ri_b, nullptr, (__nv_bfloat16*)p_rh_h, (__nv_bfloat16*)p_rh_l,
        S_TOK, INTR, HID);
    // res GEMM2: [8192,4096]@[4096,1024] -> rmlp (fp32)
    mma_gemm<0><<<dim3(HID / BN, S_TOK / BM, 1), 256, SMEM_BYTES>>>(
        (const __nv_bfloat16*)p_rh_h, (const __nv_bfloat16*)p_rh_l,
        (const __nv_bfloat16*)p_roT_h, (const __nv_bfloat16*)p_roT_l,
        ro_b, (float*)p_rmlp, nullptr, nullptr,
        S_TOK, HID, INTR);

    combine_kernel<<<S_TOK, 256>>>(x, out);
}

// round 4
// speedup vs baseline: 3.9385x; 1.3159x over previous
#include <cuda_runtime.h>
#include <cuda_fp16.h>
#include <cstdint>
#include <math.h>

#define S_TOK 8192
#define HID   1024
#define INTR  4096
#define NE    8
#define CAP   1024

#define BM 128
#define BN 128
#define BK 64               // fp16 elements per k-tile (128 bytes/row)
#define TILE_BYTES  16384   // 128 rows x 128B
#define STAGE_BYTES 49152   // 3 tensors (Ah, Al, Bh)
#define NSTAGE 3
#define SMEM_BYTES  (NSTAGE * STAGE_BYTES)

// ---------------- device scratch (no allocation allowed) ----------------
__device__ __half g_attn_h[S_TOK * HID];
__device__ __half g_attn_l[S_TOK * HID];
__device__ __half g_disp_h[NE * CAP * HID];
__device__ __half g_disp_l[NE * CAP * HID];
__device__ __half g_h_h[NE * CAP * INTR];
__device__ __half g_h_l[NE * CAP * INTR];
__device__ float  g_eo[NE * CAP * HID];
__device__ __half g_rh_h[S_TOK * INTR];
__device__ __half g_rh_l[S_TOK * INTR];
__device__ float  g_rmlp[S_TOK * HID];
__device__ __half g_iwT[NE * INTR * HID];  // [e][N=INTR][K=HID] fp16
__device__ __half g_owT[NE * HID * INTR];  // [e][N=HID][K=INTR]
__device__ __half g_riT[INTR * HID];
__device__ __half g_roT[HID * INTR];
__device__ int   g_expidx[S_TOK];
__device__ int   g_dest[S_TOK];
__device__ int   g_tos[NE * CAP];
__device__ float g_gate[S_TOK];
__device__ float g_coef0[S_TOK];
__device__ float g_coef1[S_TOK];

// ---------------- helpers ----------------
__device__ __forceinline__ float gelu_tanh(float x) {
    float x3 = x * x * x;
    return 0.5f * x * (1.f + tanhf(0.7978845608028654f * (x + 0.044715f * x3)));
}

__device__ __forceinline__ uint32_t smem_u32(const void* p) {
    uint32_t a;
    asm("{ .reg .u64 t; cvta.to.shared.u64 t, %1; cvt.u32.u64 %0, t; }" : "=r"(a) : "l"(p));
    return a;
}

__device__ __forceinline__ void ldsm_x4(uint32_t (&r)[4], uint32_t addr) {
    asm volatile("ldmatrix.sync.aligned.m8n8.x4.shared.b16 {%0,%1,%2,%3}, [%4];"
                 : "=r"(r[0]), "=r"(r[1]), "=r"(r[2]), "=r"(r[3]) : "r"(addr));
}

__device__ __forceinline__ void mma16816(float (&c)[4], const uint32_t (&a)[4],
                                         const uint32_t* b) {
    asm volatile(
        "mma.sync.aligned.m16n8k16.row.col.f32.f16.f16.f32 "
        "{%0,%1,%2,%3}, {%4,%5,%6,%7}, {%8,%9}, {%0,%1,%2,%3};"
        : "+f"(c[0]), "+f"(c[1]), "+f"(c[2]), "+f"(c[3])
        : "r"(a[0]), "r"(a[1]), "r"(a[2]), "r"(a[3]), "r"(b[0]), "r"(b[1]));
}

#define CP_ASYNC16(sm, gm) asm volatile("cp.async.cg.shared.global [%0], [%1], 16;" :: "r"(sm), "l"(gm))
#define CP_COMMIT()        asm volatile("cp.async.commit_group;" ::: "memory")
#define CP_WAIT(n)         asm volatile("cp.async.wait_group %0;" :: "n"(n) : "memory")

__device__ __forceinline__ void split_fp16(float v, __half& h, __half& l) {
    h = __float2half_rn(v);
    l = __float2half_rn(v - __half2float(h));
}

// ===========================================================================
// LayerNorm + gate logits + res_coef; emits attn as fp16 hi/lo
// ===========================================================================
__global__ void ln_gate_kernel(const float* __restrict__ x,
                               const float* __restrict__ nw,
                               const float* __restrict__ nb,
                               const float* __restrict__ wg,
                               const float* __restrict__ res_coef) {
    __shared__ float row[HID];
    __shared__ float rs[10], rq[10];
    __shared__ float dots[10];
    __shared__ float s_mean, s_rstd;

    const int s = blockIdx.x;
    const int tid = threadIdx.x;
    const int lane = tid & 31;
    const int w = tid >> 5;

    const float* xr = x + (size_t)s * HID;
    float sum = 0.f, sq = 0.f;
    for (int i = tid; i < HID; i += 320) {
        float v = xr[i];
        row[i] = v;
        sum += v; sq += v * v;
    }
    #pragma unroll
    for (int o = 16; o > 0; o >>= 1) {
        sum += __shfl_down_sync(0xffffffffu, sum, o);
        sq  += __shfl_down_sync(0xffffffffu, sq,  o);
    }
    if (lane == 0) { rs[w] = sum; rq[w] = sq; }
    __syncthreads();
    if (tid == 0) {
        float ts = 0.f, tq = 0.f;
        #pragma unroll
        for (int i = 0; i < 10; i++) { ts += rs[i]; tq += rq[i]; }
        float mean = ts * (1.f / HID);
        float var  = tq * (1.f / HID) - mean * mean;
        s_mean = mean;
        s_rstd = rsqrtf(var + 1e-12f);
    }
    __syncthreads();
    const float mean = s_mean, rstd = s_rstd;
    for (int i = tid; i < HID; i += 320) {
        float v = (row[i] - mean) * rstd * nw[i] + nb[i];
        row[i] = v;
        __half h, l;
        split_fp16(v, h, l);
        g_attn_h[(size_t)s * HID + i] = h;
        g_attn_l[(size_t)s * HID + i] = l;
    }
    __syncthreads();

    float d = 0.f;
    if (w < 8) {
        for (int m = lane; m < HID; m += 32) d += row[m] * wg[m * NE + w];
    } else {
        int c = w - 8;
        for (int m = lane; m < HID; m += 32) d += row[m] * res_coef[m * 2 + c];
    }
    #pragma unroll
    for (int o = 16; o > 0; o >>= 1) d += __shfl_down_sync(0xffffffffu, d, o);
    if (lane == 0) dots[w] = d;
    __syncthreads();

    if (tid == 0) {
        float mx = dots[0]; int am = 0;
        #pragma unroll
        for (int e = 1; e < 8; e++) if (dots[e] > mx) { mx = dots[e]; am = e; }
        float se = 0.f;
        #pragma unroll
        for (int e = 0; e < 8; e++) se += expf(dots[e] - mx);
        g_expidx[s] = am;
        g_gate[s] = 1.f / se;
        float a = dots[8], b = dots[9];
        float m2 = fmaxf(a, b);
        float ea = expf(a - m2), eb = expf(b - m2);
        float inv = 1.f / (ea + eb);
        g_coef0[s] = ea * inv;
        g_coef1[s] = eb * inv;
    }
}

// ===========================================================================
__global__ void scan_kernel() {
    const int tid = threadIdx.x;
    for (int i = tid; i < NE * CAP; i += 256) g_tos[i] = -1;
    __syncthreads();
    const int lane = tid & 31;
    const int e = tid >> 5;
    int count = 0;
    for (int base = 0; base < S_TOK; base += 32) {
        int s = base + lane;
        bool sel = (g_expidx[s] == e);
        unsigned mask = __ballot_sync(0xffffffffu, sel);
        if (sel) {
            int c = count + __popc(mask & ((1u << lane) - 1u));
            if (c < CAP) {
                g_dest[s] = e * CAP + c;
                g_tos[e * CAP + c] = s;
            } else {
                g_dest[s] = -1;
            }
        }
        count += __popc(mask);
    }
}

// ===========================================================================
__global__ void dispatch_kernel() {
    const int slot = blockIdx.x;
    const int tid = threadIdx.x;
    const int t = g_tos[slot];
    uint2* dh = (uint2*)(g_disp_h + (size_t)slot * HID);
    uint2* dl = (uint2*)(g_disp_l + (size_t)slot * HID);
    if (t >= 0) {
        dh[tid] = ((const uint2*)(g_attn_h + (size_t)t * HID))[tid];
        dl[tid] = ((const uint2*)(g_attn_l + (size_t)t * HID))[tid];
    } else {
        dh[tid] = make_uint2(0u, 0u);
        dl[tid] = make_uint2(0u, 0u);
    }
}

// ===========================================================================
// Weight transpose + fp16 convert: W [K,N] fp32 -> T [N,K] fp16
// ===========================================================================
__global__ void wconv_kernel(const float* __restrict__ W,
                             __half* __restrict__ T,
                             int K, int N) {
    __shared__ float tile[32][33];
    const int n0 = blockIdx.x * 32;
    const int k0 = blockIdx.y * 32;
    const long zb = blockIdx.z;
    W += zb * (long)K * N;
    T += zb * (long)K * N;
    const int tx = threadIdx.x, ty = threadIdx.y;
    #pragma unroll
    for (int j = 0; j < 4; j++) {
        int r = ty + j * 8;
        tile[r][tx] = W[(size_t)(k0 + r) * N + n0 + tx];
    }
    __syncthreads();
    #pragma unroll
    for (int j = 0; j < 4; j++) {
        int r = ty + j * 8;
        T[(size_t)(n0 + r) * K + k0 + tx] = __float2half_rn(tile[tx][r]);
    }
}

// ===========================================================================
// mma.sync fp16 2-term GEMM: C = act((Ah+Al) @ Bh^T + bias)
// A: [M,K] K-major hi/lo fp16. B: [N,K] K-major single fp16.
// BM=BN=128, BK=64, 256 threads (8 warps, 2m x 4n), warp tile 64x32.
// 3-stage cp.async pipeline, xor swizzle (128B rows).
// ACT=1: gelu, emit fp16 hi/lo. ACT=0: emit fp32.
// ===========================================================================
template <int ACT>
__global__ __launch_bounds__(256, 1)
void mma_gemm(const __half* __restrict__ Ah, const __half* __restrict__ Al,
              const __half* __restrict__ Bh,
              const float* __restrict__ bias,
              float* __restrict__ Cf,
              __half* __restrict__ Ch, __half* __restrict__ Cl,
              int M, int N, int K) {
    extern __shared__ char smem[];
    const uint32_t sbase = smem_u32(smem);
    const int tid = threadIdx.x;
    const int lane = tid & 31;
    const int wid = tid >> 5;
    const int wm = wid >> 2;          // 0..1 -> warp row (64 rows each)
    const int wn = wid & 3;           // 0..3 -> warp col (32 cols each)
    const long bz = blockIdx.z;
    const int m0 = blockIdx.y * BM;
    const int n0 = blockIdx.x * BN;

    const __half* srcs[3] = {
        Ah + bz * (long)M * K + (size_t)m0 * K,
        Al + bz * (long)M * K + (size_t)m0 * K,
        Bh + bz * (long)N * K + (size_t)n0 * K
    };
    bias += bz * (long)N;

    const int lrow0 = tid >> 3;        // rows tid/8 + 32*i
    const int lch   = tid & 7;         // 16B chunk within 128B row

    float acc[4][4][4];
    #pragma unroll
    for (int a = 0; a < 4; a++)
        #pragma unroll
        for (int b = 0; b < 4; b++)
            #pragma unroll
            for (int c = 0; c < 4; c++) acc[a][b][c] = 0.f;

    const int NT = K / BK;

    auto load_stage = [&](int st, int kt) {
        const uint32_t stb = sbase + (uint32_t)st * STAGE_BYTES;
        #pragma unroll
        for (int t = 0; t < 3; t++) {
            const __half* g = srcs[t] + kt + lch * 8;
            const uint32_t tb = stb + (uint32_t)t * TILE_BYTES;
            #pragma unroll
            for (int i = 0; i < 4; i++) {
                int row = lrow0 + i * 32;
                uint32_t sm = tb + (uint32_t)(row * 128 + ((lch ^ (row & 7)) << 4));
                CP_ASYNC16(sm, g + (size_t)row * K);
            }
        }
    };

    load_stage(0, 0);
    CP_COMMIT();
    if (NT > 1) { load_stage(1, BK); CP_COMMIT(); }

    for (int s = 0; s < NT; s++) {
        if (s + 1 < NT) CP_WAIT(1); else CP_WAIT(0);
        __syncthreads();

        // prefetch stage s+2 (writes buffer (s+2)%3, last read in stage s-1)
        if (s + 2 < NT) { load_stage((s + 2) % NSTAGE, (s + 2) * BK); CP_COMMIT(); }

        const uint32_t stb = sbase + (uint32_t)(s % NSTAGE) * STAGE_BYTES;
        const uint32_t Ahb = stb, Alb = stb + TILE_BYTES, Bhb = stb + 2 * TILE_BYTES;

        const int g = lane >> 3;       // ldmatrix address group
        const int li = lane & 7;

        #pragma unroll
        for (int kk = 0; kk < 4; kk++) {
            uint32_t ah[4][4], al[4][4];
            {
                const int arow_b = wm * 64 + (g & 1) * 8 + li;
                const int ach = kk * 2 + (g >> 1);
                #pragma unroll
                for (int mf = 0; mf < 4; mf++) {
                    int r = arow_b + mf * 16;
                    uint32_t off = (uint32_t)(r * 128 + ((ach ^ (r & 7)) << 4));
                    ldsm_x4(ah[mf], Ahb + off);
                    ldsm_x4(al[mf], Alb + off);
                }
            }
            uint32_t bh[4][2];
            {
                const int brow_b = wn * 32 + (g >> 1) * 8 + li;
                const int bch = kk * 2 + (g & 1);
                #pragma unroll
                for (int nb = 0; nb < 2; nb++) {
                    int r = brow_b + nb * 16;
                    uint32_t off = (uint32_t)(r * 128 + ((bch ^ (r & 7)) << 4));
                    uint32_t t4[4];
                    ldsm_x4(t4, Bhb + off);
                    bh[nb * 2][0] = t4[0]; bh[nb * 2][1] = t4[1];
                    bh[nb * 2 + 1][0] = t4[2]; bh[nb * 2 + 1][1] = t4[3];
                }
            }
            #pragma unroll
            for (int mf = 0; mf < 4; mf++)
                #pragma unroll
                for (int nf = 0; nf < 4; nf++) {
                    mma16816(acc[mf][nf], ah[mf], bh[nf]);
                    mma16816(acc[mf][nf], al[mf], bh[nf]);
                }
        }
        __syncthreads();
    }

    // ---- epilogue ----
    const int mrow = m0 + wm * 64 + (lane >> 2);
    const int ncol0 = n0 + wn * 32 + (lane & 3) * 2;
    #pragma unroll
    for (int nf = 0; nf < 4; nf++) {
        const int n = ncol0 + nf * 8;
        const float bv0 = bias[n], bv1 = bias[n + 1];
        #pragma unroll
        for (int mf = 0; mf < 4; mf++) {
            const float* c = acc[mf][nf];
            const int m_a = mrow + mf * 16;
            const int m_b = m_a + 8;
            if (ACT) {
                float v00 = gelu_tanh(c[0] + bv0), v01 = gelu_tanh(c[1] + bv1);
                float v10 = gelu_tanh(c[2] + bv0), v11 = gelu_tanh(c[3] + bv1);
                __half h0, l0, h1, l1;
                split_fp16(v00, h0, l0); split_fp16(v01, h1, l1);
                uint32_t ph = (uint32_t)__half_as_ushort(h0) |
                              ((uint32_t)__half_as_ushort(h1) << 16);
                uint32_t pl = (uint32_t)__half_as_ushort(l0) |
                              ((uint32_t)__half_as_ushort(l1) << 16);
                *(uint32_t*)(Ch + bz * (long)M * N + (size_t)m_a * N + n) = ph;
                *(uint32_t*)(Cl + bz * (long)M * N + (size_t)m_a * N + n) = pl;
                split_fp16(v10, h0, l0); split_fp16(v11, h1, l1);
                ph = (uint32_t)__half_as_ushort(h0) |
                     ((uint32_t)__half_as_ushort(h1) << 16);
                pl = (uint32_t)__half_as_ushort(l0) |
                     ((uint32_t)__half_as_ushort(l1) << 16);
                *(uint32_t*)(Ch + bz * (long)M * N + (size_t)m_b * N + n) = ph;
                *(uint32_t*)(Cl + bz * (long)M * N + (size_t)m_b * N + n) = pl;
            } else {
                float2 r0 = make_float2(c[0] + bv0, c[1] + bv1);
                float2 r1 = make_float2(c[2] + bv0, c[3] + bv1);
                *(float2*)(Cf + bz * (long)M * N + (size_t)m_a * N + n) = r0;
                *(float2*)(Cf + bz * (long)M * N + (size_t)m_b * N + n) = r1;
            }
        }
    }
}

// ===========================================================================
__global__ void combine_kernel(const float* __restrict__ x, float* __restrict__ out) {
    const int s = blockIdx.x;
    const int tid = threadIdx.x;
    const int d = g_dest[s];
    const float c0 = g_coef0[s];
    const float c1g = g_coef1[s] * g_gate[s];

    float4 xv = ((const float4*)(x + (size_t)s * HID))[tid];
    float4 rv = ((const float4*)(g_rmlp + (size_t)s * HID))[tid];
    float4 ev = (d >= 0) ? ((const float4*)(g_eo + (size_t)d * HID))[tid]
                         : make_float4(0.f, 0.f, 0.f, 0.f);
    float4 o;
    o.x = xv.x + c0 * rv.x + c1g * ev.x;
    o.y = xv.y + c0 * rv.y + c1g * ev.y;
    o.z = xv.z + c0 * rv.z + c1g * ev.z;
    o.w = xv.w + c0 * rv.w + c1g * ev.w;
    ((float4*)(out + (size_t)s * HID))[tid] = o;
}

// ===========================================================================
extern "C" void kernel_launch(void* const* d_in, const int* in_sizes, int n_in,
                              void* d_out, int out_size) {
    const float* x       = (const float*)d_in[0];
    const float* attn_nw = (const float*)d_in[1];
    const float* attn_nb = (const float*)d_in[2];
    const float* wg      = (const float*)d_in[3];
    const float* inter_w = (const float*)d_in[4];
    const float* inter_b = (const float*)d_in[5];
    const float* out_w   = (const float*)d_in[6];
    const float* out_b   = (const float*)d_in[7];
    const float* ri_w    = (const float*)d_in[8];
    const float* ri_b    = (const float*)d_in[9];
    const float* ro_w    = (const float*)d_in[10];
    const float* ro_b    = (const float*)d_in[11];
    const float* rcoef   = (const float*)d_in[12];
    float* out = (float*)d_out;

    cudaFuncSetAttribute(mma_gemm<0>, cudaFuncAttributeMaxDynamicSharedMemorySize, SMEM_BYTES);
    cudaFuncSetAttribute(mma_gemm<1>, cudaFuncAttributeMaxDynamicSharedMemorySize, SMEM_BYTES);

    void *p_disp_h, *p_disp_l, *p_h_h, *p_h_l, *p_eo, *p_attn_h, *p_attn_l;
    void *p_rh_h, *p_rh_l, *p_rmlp;
    void *p_iwT, *p_owT, *p_riT, *p_roT;
    cudaGetSymbolAddress(&p_disp_h, g_disp_h);
    cudaGetSymbolAddress(&p_disp_l, g_disp_l);
    cudaGetSymbolAddress(&p_h_h, g_h_h);
    cudaGetSymbolAddress(&p_h_l, g_h_l);
    cudaGetSymbolAddress(&p_eo, g_eo);
    cudaGetSymbolAddress(&p_attn_h, g_attn_h);
    cudaGetSymbolAddress(&p_attn_l, g_attn_l);
    cudaGetSymbolAddress(&p_rh_h, g_rh_h);
    cudaGetSymbolAddress(&p_rh_l, g_rh_l);
    cudaGetSymbolAddress(&p_rmlp, g_rmlp);
    cudaGetSymbolAddress(&p_iwT, g_iwT);
    cudaGetSymbolAddress(&p_owT, g_owT);
    cudaGetSymbolAddress(&p_riT, g_riT);
    cudaGetSymbolAddress(&p_roT, g_roT);

    dim3 wb(32, 8);
    wconv_kernel<<<dim3(INTR / 32, HID / 32, NE), wb>>>(inter_w, (__half*)p_iwT, HID, INTR);
    wconv_kernel<<<dim3(HID / 32, INTR / 32, NE), wb>>>(out_w, (__half*)p_owT, INTR, HID);
    wconv_kernel<<<dim3(INTR / 32, HID / 32, 1), wb>>>(ri_w, (__half*)p_riT, HID, INTR);
    wconv_kernel<<<dim3(HID / 32, INTR / 32, 1), wb>>>(ro_w, (__half*)p_roT, INTR, HID);

    ln_gate_kernel<<<S_TOK, 320>>>(x, attn_nw, attn_nb, wg, rcoef);
    scan_kernel<<<1, 256>>>();
    dispatch_kernel<<<NE * CAP, 256>>>();

    // expert GEMM1 + GELU: [1024,1024]@[1024,4096] x8 -> h (fp16 hi/lo)
    mma_gemm<1><<<dim3(INTR / BN, CAP / BM, NE), 256, SMEM_BYTES>>>(
        (const __half*)p_disp_h, (const __half*)p_disp_l, (const __half*)p_iwT,
        inter_b, nullptr, (__half*)p_h_h, (__half*)p_h_l,
        CAP, INTR, HID);
    // expert GEMM2: [1024,4096]@[4096,1024] x8 -> eo (fp32)
    mma_gemm<0><<<dim3(HID / BN, CAP / BM, NE), 256, SMEM_BYTES>>>(
        (const __half*)p_h_h, (const __half*)p_h_l, (const __half*)p_owT,
        out_b, (float*)p_eo, nullptr, nullptr,
        CAP, HID, INTR);
    // res GEMM1 + GELU: [8192,1024]@[1024,4096] -> rh (fp16 hi/lo)
    mma_gemm<1><<<dim3(INTR / BN, S_TOK / BM, 1), 256, SMEM_BYTES>>>(
        (const __half*)p_attn_h, (const __half*)p_attn_l, (const __half*)p_riT,
        ri_b, nullptr, (__half*)p_rh_h, (__half*)p_rh_l,
        S_TOK, INTR, HID);
    // res GEMM2: [8192,4096]@[4096,1024] -> rmlp (fp32)
    mma_gemm<0><<<dim3(HID / BN, S_TOK / BM, 1), 256, SMEM_BYTES>>>(
        (const __half*)p_rh_h, (const __half*)p_rh_l, (const __half*)p_roT,
        ro_b, (float*)p_rmlp, nullptr, nullptr,
        S_TOK, HID, INTR);

    combine_kernel<<<S_TOK, 256>>>(x, out);
}

// round 5
// speedup vs baseline: 5.7952x; 1.4714x over previous
#include <cuda_runtime.h>
#include <cuda_fp16.h>
#include <cstdint>
#include <math.h>

#define S_TOK 8192
#define HID   1024
#define INTR  4096
#define NE    8
#define CAP   1024

#define BM 128
#define BN 128
#define BK 64               // fp16 elements per k-tile (128 bytes/row)
#define TILE_BYTES  16384   // 128 rows x 128B
#define STAGE_BYTES 32768   // 2 tensors (A, B)
#define NSTAGE 4
#define SMEM_BYTES  (NSTAGE * STAGE_BYTES)

// ---------------- device scratch (no allocation allowed) ----------------
__device__ __half g_attn[S_TOK * HID];
__device__ __half g_disp[NE * CAP * HID];
__device__ __half g_h[NE * CAP * INTR];
__device__ float  g_eo[NE * CAP * HID];
__device__ __half g_rh[S_TOK * INTR];
__device__ float  g_rmlp[S_TOK * HID];
__device__ __half g_iwT[NE * INTR * HID];  // [e][N=INTR][K=HID] fp16
__device__ __half g_owT[NE * HID * INTR];  // [e][N=HID][K=INTR]
__device__ __half g_riT[INTR * HID];
__device__ __half g_roT[HID * INTR];
__device__ int   g_expidx[S_TOK];
__device__ int   g_dest[S_TOK];
__device__ int   g_tos[NE * CAP];
__device__ float g_gate[S_TOK];
__device__ float g_coef0[S_TOK];
__device__ float g_coef1[S_TOK];

// ---------------- helpers ----------------
__device__ __forceinline__ float gelu_tanh(float x) {
    float x3 = x * x * x;
    return 0.5f * x * (1.f + tanhf(0.7978845608028654f * (x + 0.044715f * x3)));
}

__device__ __forceinline__ uint32_t smem_u32(const void* p) {
    uint32_t a;
    asm("{ .reg .u64 t; cvta.to.shared.u64 t, %1; cvt.u32.u64 %0, t; }" : "=r"(a) : "l"(p));
    return a;
}

__device__ __forceinline__ void ldsm_x4(uint32_t (&r)[4], uint32_t addr) {
    asm volatile("ldmatrix.sync.aligned.m8n8.x4.shared.b16 {%0,%1,%2,%3}, [%4];"
                 : "=r"(r[0]), "=r"(r[1]), "=r"(r[2]), "=r"(r[3]) : "r"(addr));
}

__device__ __forceinline__ void mma16816(float (&c)[4], const uint32_t (&a)[4],
                                         const uint32_t* b) {
    asm volatile(
        "mma.sync.aligned.m16n8k16.row.col.f32.f16.f16.f32 "
        "{%0,%1,%2,%3}, {%4,%5,%6,%7}, {%8,%9}, {%0,%1,%2,%3};"
        : "+f"(c[0]), "+f"(c[1]), "+f"(c[2]), "+f"(c[3])
        : "r"(a[0]), "r"(a[1]), "r"(a[2]), "r"(a[3]), "r"(b[0]), "r"(b[1]));
}

#define CP_ASYNC16(sm, gm) asm volatile("cp.async.cg.shared.global [%0], [%1], 16;" :: "r"(sm), "l"(gm))
#define CP_COMMIT()        asm volatile("cp.async.commit_group;" ::: "memory")
#define CP_WAIT(n)         asm volatile("cp.async.wait_group %0;" :: "n"(n) : "memory")

// ===========================================================================
// LayerNorm + gate logits + res_coef; emits attn as fp16
// ===========================================================================
__global__ void ln_gate_kernel(const float* __restrict__ x,
                               const float* __restrict__ nw,
                               const float* __restrict__ nb,
                               const float* __restrict__ wg,
                               const float* __restrict__ res_coef) {
    __shared__ float row[HID];
    __shared__ float rs[10], rq[10];
    __shared__ float dots[10];
    __shared__ float s_mean, s_rstd;

    const int s = blockIdx.x;
    const int tid = threadIdx.x;
    const int lane = tid & 31;
    const int w = tid >> 5;

    const float* xr = x + (size_t)s * HID;
    float sum = 0.f, sq = 0.f;
    for (int i = tid; i < HID; i += 320) {
        float v = xr[i];
        row[i] = v;
        sum += v; sq += v * v;
    }
    #pragma unroll
    for (int o = 16; o > 0; o >>= 1) {
        sum += __shfl_down_sync(0xffffffffu, sum, o);
        sq  += __shfl_down_sync(0xffffffffu, sq,  o);
    }
    if (lane == 0) { rs[w] = sum; rq[w] = sq; }
    __syncthreads();
    if (tid == 0) {
        float ts = 0.f, tq = 0.f;
        #pragma unroll
        for (int i = 0; i < 10; i++) { ts += rs[i]; tq += rq[i]; }
        float mean = ts * (1.f / HID);
        float var  = tq * (1.f / HID) - mean * mean;
        s_mean = mean;
        s_rstd = rsqrtf(var + 1e-12f);
    }
    __syncthreads();
    const float mean = s_mean, rstd = s_rstd;
    for (int i = tid; i < HID; i += 320) {
        float v = (row[i] - mean) * rstd * nw[i] + nb[i];
        row[i] = v;
        g_attn[(size_t)s * HID + i] = __float2half_rn(v);
    }
    __syncthreads();

    float d = 0.f;
    if (w < 8) {
        for (int m = lane; m < HID; m += 32) d += row[m] * wg[m * NE + w];
    } else {
        int c = w - 8;
        for (int m = lane; m < HID; m += 32) d += row[m] * res_coef[m * 2 + c];
    }
    #pragma unroll
    for (int o = 16; o > 0; o >>= 1) d += __shfl_down_sync(0xffffffffu, d, o);
    if (lane == 0) dots[w] = d;
    __syncthreads();

    if (tid == 0) {
        float mx = dots[0]; int am = 0;
        #pragma unroll
        for (int e = 1; e < 8; e++) if (dots[e] > mx) { mx = dots[e]; am = e; }
        float se = 0.f;
        #pragma unroll
        for (int e = 0; e < 8; e++) se += expf(dots[e] - mx);
        g_expidx[s] = am;
        g_gate[s] = 1.f / se;
        float a = dots[8], b = dots[9];
        float m2 = fmaxf(a, b);
        float ea = expf(a - m2), eb = expf(b - m2);
        float inv = 1.f / (ea + eb);
        g_coef0[s] = ea * inv;
        g_coef1[s] = eb * inv;
    }
}

// ===========================================================================
__global__ void scan_kernel() {
    const int tid = threadIdx.x;
    for (int i = tid; i < NE * CAP; i += 256) g_tos[i] = -1;
    __syncthreads();
    const int lane = tid & 31;
    const int e = tid >> 5;
    int count = 0;
    for (int base = 0; base < S_TOK; base += 32) {
        int s = base + lane;
        bool sel = (g_expidx[s] == e);
        unsigned mask = __ballot_sync(0xffffffffu, sel);
        if (sel) {
            int c = count + __popc(mask & ((1u << lane) - 1u));
            if (c < CAP) {
                g_dest[s] = e * CAP + c;
                g_tos[e * CAP + c] = s;
            } else {
                g_dest[s] = -1;
            }
        }
        count += __popc(mask);
    }
}

// ===========================================================================
// Dispatch scatter: 64 threads per slot (128 fp16 via uint2 x 2)
// ===========================================================================
__global__ void dispatch_kernel() {
    const int slot = blockIdx.x;
    const int tid = threadIdx.x;
    const int t = g_tos[slot];
    uint4* dst = (uint4*)(g_disp + (size_t)slot * HID);
    if (t >= 0) {
        dst[tid] = ((const uint4*)(g_attn + (size_t)t * HID))[tid];
    } else {
        dst[tid] = make_uint4(0u, 0u, 0u, 0u);
    }
}

// ===========================================================================
// Weight transpose + fp16 convert: W [K,N] fp32 -> T [N,K] fp16
// ===========================================================================
__global__ void wconv_kernel(const float* __restrict__ W,
                             __half* __restrict__ T,
                             int K, int N) {
    __shared__ float tile[32][33];
    const int n0 = blockIdx.x * 32;
    const int k0 = blockIdx.y * 32;
    const long zb = blockIdx.z;
    W += zb * (long)K * N;
    T += zb * (long)K * N;
    const int tx = threadIdx.x, ty = threadIdx.y;
    #pragma unroll
    for (int j = 0; j < 4; j++) {
        int r = ty + j * 8;
        tile[r][tx] = W[(size_t)(k0 + r) * N + n0 + tx];
    }
    __syncthreads();
    #pragma unroll
    for (int j = 0; j < 4; j++) {
        int r = ty + j * 8;
        T[(size_t)(n0 + r) * K + k0 + tx] = __float2half_rn(tile[tx][r]);
    }
}

// ===========================================================================
// mma.sync fp16 GEMM: C = act(A @ B^T + bias)
// A: [M,K] K-major fp16. B: [N,K] K-major fp16.
// BM=BN=128, BK=64, 256 threads (8 warps, 2m x 4n), warp tile 64x32.
// 4-stage cp.async pipeline, xor swizzle (128B rows).
// ACT=1: gelu, emit fp16. ACT=0: emit fp32.
// ===========================================================================
template <int ACT>
__global__ __launch_bounds__(256, 1)
void mma_gemm(const __half* __restrict__ A, const __half* __restrict__ B,
              const float* __restrict__ bias,
              float* __restrict__ Cf, __half* __restrict__ Ch,
              int M, int N, int K) {
    extern __shared__ char smem[];
    const uint32_t sbase = smem_u32(smem);
    const int tid = threadIdx.x;
    const int lane = tid & 31;
    const int wid = tid >> 5;
    const int wm = wid >> 2;          // 0..1 -> warp row (64 rows each)
    const int wn = wid & 3;           // 0..3 -> warp col (32 cols each)
    const long bz = blockIdx.z;
    const int m0 = blockIdx.y * BM;
    const int n0 = blockIdx.x * BN;

    const __half* srcs[2] = {
        A + bz * (long)M * K + (size_t)m0 * K,
        B + bz * (long)N * K + (size_t)n0 * K
    };
    bias += bz * (long)N;

    const int lrow0 = tid >> 3;        // rows tid/8 + 32*i
    const int lch   = tid & 7;         // 16B chunk within 128B row

    float acc[4][4][4];
    #pragma unroll
    for (int a = 0; a < 4; a++)
        #pragma unroll
        for (int b = 0; b < 4; b++)
            #pragma unroll
            for (int c = 0; c < 4; c++) acc[a][b][c] = 0.f;

    const int NT = K / BK;

    auto load_stage = [&](int st, int kt) {
        const uint32_t stb = sbase + (uint32_t)st * STAGE_BYTES;
        #pragma unroll
        for (int t = 0; t < 2; t++) {
            const __half* g = srcs[t] + kt + lch * 8;
            const uint32_t tb = stb + (uint32_t)t * TILE_BYTES;
            #pragma unroll
            for (int i = 0; i < 4; i++) {
                int row = lrow0 + i * 32;
                uint32_t sm = tb + (uint32_t)(row * 128 + ((lch ^ (row & 7)) << 4));
                CP_ASYNC16(sm, g + (size_t)row * K);
            }
        }
    };

    // prime NSTAGE-1 stages
    #pragma unroll
    for (int p = 0; p < NSTAGE - 1; p++) {
        if (p < NT) { load_stage(p, p * BK); CP_COMMIT(); }
    }

    for (int s = 0; s < NT; s++) {
        if (s + NSTAGE - 1 < NT) CP_WAIT(NSTAGE - 2);
        else if (s + NSTAGE - 2 < NT) CP_WAIT(NSTAGE - 3);
        else if (s + NSTAGE - 3 < NT) CP_WAIT(NSTAGE - 4);
        else CP_WAIT(0);
        __syncthreads();

        if (s + NSTAGE - 1 < NT) {
            load_stage((s + NSTAGE - 1) % NSTAGE, (s + NSTAGE - 1) * BK);
            CP_COMMIT();
        }

        const uint32_t stb = sbase + (uint32_t)(s % NSTAGE) * STAGE_BYTES;
        const uint32_t Ab = stb, Bb = stb + TILE_BYTES;

        const int g = lane >> 3;       // ldmatrix address group
        const int li = lane & 7;

        #pragma unroll
        for (int kk = 0; kk < 4; kk++) {
            uint32_t af[4][4];
            {
                const int arow_b = wm * 64 + (g & 1) * 8 + li;
                const int ach = kk * 2 + (g >> 1);
                #pragma unroll
                for (int mf = 0; mf < 4; mf++) {
                    int r = arow_b + mf * 16;
                    uint32_t off = (uint32_t)(r * 128 + ((ach ^ (r & 7)) << 4));
                    ldsm_x4(af[mf], Ab + off);
                }
            }
            uint32_t bf[4][2];
            {
                const int brow_b = wn * 32 + (g >> 1) * 8 + li;
                const int bch = kk * 2 + (g & 1);
                #pragma unroll
                for (int nb = 0; nb < 2; nb++) {
                    int r = brow_b + nb * 16;
                    uint32_t off = (uint32_t)(r * 128 + ((bch ^ (r & 7)) << 4));
                    uint32_t t4[4];
                    ldsm_x4(t4, Bb + off);
                    bf[nb * 2][0] = t4[0]; bf[nb * 2][1] = t4[1];
                    bf[nb * 2 + 1][0] = t4[2]; bf[nb * 2 + 1][1] = t4[3];
                }
            }
            #pragma unroll
            for (int mf = 0; mf < 4; mf++)
                #pragma unroll
                for (int nf = 0; nf < 4; nf++)
                    mma16816(acc[mf][nf], af[mf], bf[nf]);
        }
        __syncthreads();
    }

    // ---- epilogue ----
    const int mrow = m0 + wm * 64 + (lane >> 2);
    const int ncol0 = n0 + wn * 32 + (lane & 3) * 2;
    #pragma unroll
    for (int nf = 0; nf < 4; nf++) {
        const int n = ncol0 + nf * 8;
        const float bv0 = bias[n], bv1 = bias[n + 1];
        #pragma unroll
        for (int mf = 0; mf < 4; mf++) {
            const float* c = acc[mf][nf];
            const int m_a = mrow + mf * 16;
            const int m_b = m_a + 8;
            if (ACT) {
                float v00 = gelu_tanh(c[0] + bv0), v01 = gelu_tanh(c[1] + bv1);
                float v10 = gelu_tanh(c[2] + bv0), v11 = gelu_tanh(c[3] + bv1);
                uint32_t p0 = (uint32_t)__half_as_ushort(__float2half_rn(v00)) |
                              ((uint32_t)__half_as_ushort(__float2half_rn(v01)) << 16);
                uint32_t p1 = (uint32_t)__half_as_ushort(__float2half_rn(v10)) |
                              ((uint32_t)__half_as_ushort(__float2half_rn(v11)) << 16);
                *(uint32_t*)(Ch + bz * (long)M * N + (size_t)m_a * N + n) = p0;
                *(uint32_t*)(Ch + bz * (long)M * N + (size_t)m_b * N + n) = p1;
            } else {
                float2 r0 = make_float2(c[0] + bv0, c[1] + bv1);
                float2 r1 = make_float2(c[2] + bv0, c[3] + bv1);
                *(float2*)(Cf + bz * (long)M * N + (size_t)m_a * N + n) = r0;
                *(float2*)(Cf + bz * (long)M * N + (size_t)m_b * N + n) = r1;
            }
        }
    }
}

// ===========================================================================
__global__ void combine_kernel(const float* __restrict__ x, float* __restrict__ out) {
    const int s = blockIdx.x;
    const int tid = threadIdx.x;
    const int d = g_dest[s];
    const float c0 = g_coef0[s];
    const float c1g = g_coef1[s] * g_gate[s];

    float4 xv = ((const float4*)(x + (size_t)s * HID))[tid];
    float4 rv = ((const float4*)(g_rmlp + (size_t)s * HID))[tid];
    float4 ev = (d >= 0) ? ((const float4*)(g_eo + (size_t)d * HID))[tid]
                         : make_float4(0.f, 0.f, 0.f, 0.f);
    float4 o;
    o.x = xv.x + c0 * rv.x + c1g * ev.x;
    o.y = xv.y + c0 * rv.y + c1g * ev.y;
    o.z = xv.z + c0 * rv.z + c1g * ev.z;
    o.w = xv.w + c0 * rv.w + c1g * ev.w;
    ((float4*)(out + (size_t)s * HID))[tid] = o;
}

// ===========================================================================
extern "C" void kernel_launch(void* const* d_in, const int* in_sizes, int n_in,
                              void* d_out, int out_size) {
    const float* x       = (const float*)d_in[0];
    const float* attn_nw = (const float*)d_in[1];
    const float* attn_nb = (const float*)d_in[2];
    const float* wg      = (const float*)d_in[3];
    const float* inter_w = (const float*)d_in[4];
    const float* inter_b = (const float*)d_in[5];
    const float* out_w   = (const float*)d_in[6];
    const float* out_b   = (const float*)d_in[7];
    const float* ri_w    = (const float*)d_in[8];
    const float* ri_b    = (const float*)d_in[9];
    const float* ro_w    = (const float*)d_in[10];
    const float* ro_b    = (const float*)d_in[11];
    const float* rcoef   = (const float*)d_in[12];
    float* out = (float*)d_out;

    cudaFuncSetAttribute(mma_gemm<0>, cudaFuncAttributeMaxDynamicSharedMemorySize, SMEM_BYTES);
    cudaFuncSetAttribute(mma_gemm<1>, cudaFuncAttributeMaxDynamicSharedMemorySize, SMEM_BYTES);

    void *p_disp, *p_h, *p_eo, *p_attn, *p_rh, *p_rmlp;
    void *p_iwT, *p_owT, *p_riT, *p_roT;
    cudaGetSymbolAddress(&p_disp, g_disp);
    cudaGetSymbolAddress(&p_h, g_h);
    cudaGetSymbolAddress(&p_eo, g_eo);
    cudaGetSymbolAddress(&p_attn, g_attn);
    cudaGetSymbolAddress(&p_rh, g_rh);
    cudaGetSymbolAddress(&p_rmlp, g_rmlp);
    cudaGetSymbolAddress(&p_iwT, g_iwT);
    cudaGetSymbolAddress(&p_owT, g_owT);
    cudaGetSymbolAddress(&p_riT, g_riT);
    cudaGetSymbolAddress(&p_roT, g_roT);

    dim3 wb(32, 8);
    wconv_kernel<<<dim3(INTR / 32, HID / 32, NE), wb>>>(inter_w, (__half*)p_iwT, HID, INTR);
    wconv_kernel<<<dim3(HID / 32, INTR / 32, NE), wb>>>(out_w, (__half*)p_owT, INTR, HID);
    wconv_kernel<<<dim3(INTR / 32, HID / 32, 1), wb>>>(ri_w, (__half*)p_riT, HID, INTR);
    wconv_kernel<<<dim3(HID / 32, INTR / 32, 1), wb>>>(ro_w, (__half*)p_roT, INTR, HID);

    ln_gate_kernel<<<S_TOK, 320>>>(x, attn_nw, attn_nb, wg, rcoef);
    scan_kernel<<<1, 256>>>();
    dispatch_kernel<<<NE * CAP, 128>>>();

    // expert GEMM1 + GELU: [1024,1024]@[1024,4096] x8 -> h (fp16)
    mma_gemm<1><<<dim3(INTR / BN, CAP / BM, NE), 256, SMEM_BYTES>>>(
        (const __half*)p_disp, (const __half*)p_iwT,
        inter_b, nullptr, (__half*)p_h, CAP, INTR, HID);
    // expert GEMM2: [1024,4096]@[4096,1024] x8 -> eo (fp32)
    mma_gemm<0><<<dim3(HID / BN, CAP / BM, NE), 256, SMEM_BYTES>>>(
        (const __half*)p_h, (const __half*)p_owT,
        out_b, (float*)p_eo, nullptr, CAP, HID, INTR);
    // res GEMM1 + GELU: [8192,1024]@[1024,4096] -> rh (fp16)
    mma_gemm<1><<<dim3(INTR / BN, S_TOK / BM, 1), 256, SMEM_BYTES>>>(
        (const __half*)p_attn, (const __half*)p_riT,
        ri_b, nullptr, (__half*)p_rh, S_TOK, INTR, HID);
    // res GEMM2: [8192,4096]@[4096,1024] -> rmlp (fp32)
    mma_gemm<0><<<dim3(HID / BN, S_TOK / BM, 1), 256, SMEM_BYTES>>>(
        (const __half*)p_rh, (const __half*)p_roT,
        ro_b, (float*)p_rmlp, nullptr, S_TOK, HID, INTR);

    combine_kernel<<<S_TOK, 256>>>(x, out);
}

// round 6
// speedup vs baseline: 5.8551x; 1.0103x over previous
#include <cuda_runtime.h>
#include <cuda_fp16.h>
#include <cstdint>
#include <math.h>

#define S_TOK 8192
#define HID   1024
#define INTR  4096
#define NE    8
#define CAP   1024

#define BM 128
#define BN 128
#define BK 64               // fp16 elements per k-tile (128 bytes/row)
#define TILE_BYTES  16384   // 128 rows x 128B
#define STAGE_BYTES 32768   // 2 tensors (A, B)
#define NSTAGE 4
#define SMEM_BYTES  (NSTAGE * STAGE_BYTES)

// ---------------- device scratch (no allocation allowed) ----------------
__device__ __half g_attn[S_TOK * HID];
__device__ __half g_disp[NE * CAP * HID];
__device__ __half g_h[NE * CAP * INTR];
__device__ float  g_eo[NE * CAP * HID];
__device__ __half g_rh[S_TOK * INTR];
__device__ __half g_iwT[NE * INTR * HID];  // [e][N=INTR][K=HID] fp16
__device__ __half g_owT[NE * HID * INTR];  // [e][N=HID][K=INTR]
__device__ __half g_riT[INTR * HID];
__device__ __half g_roT[HID * INTR];
__device__ int   g_expidx[S_TOK];
__device__ int   g_dest[S_TOK];
__device__ int   g_tos[NE * CAP];
__device__ float g_gate[S_TOK];
__device__ float g_coef0[S_TOK];
__device__ float g_coef1[S_TOK];

// ---------------- helpers ----------------
__device__ __forceinline__ float gelu_tanh(float x) {
    float x3 = x * x * x;
    return 0.5f * x * (1.f + tanhf(0.7978845608028654f * (x + 0.044715f * x3)));
}

__device__ __forceinline__ uint32_t smem_u32(const void* p) {
    uint32_t a;
    asm("{ .reg .u64 t; cvta.to.shared.u64 t, %1; cvt.u32.u64 %0, t; }" : "=r"(a) : "l"(p));
    return a;
}

__device__ __forceinline__ void ldsm_x4(uint32_t (&r)[4], uint32_t addr) {
    asm volatile("ldmatrix.sync.aligned.m8n8.x4.shared.b16 {%0,%1,%2,%3}, [%4];"
                 : "=r"(r[0]), "=r"(r[1]), "=r"(r[2]), "=r"(r[3]) : "r"(addr));
}

__device__ __forceinline__ void mma16816(float (&c)[4], const uint32_t (&a)[4],
                                         const uint32_t* b) {
    asm volatile(
        "mma.sync.aligned.m16n8k16.row.col.f32.f16.f16.f32 "
        "{%0,%1,%2,%3}, {%4,%5,%6,%7}, {%8,%9}, {%0,%1,%2,%3};"
        : "+f"(c[0]), "+f"(c[1]), "+f"(c[2]), "+f"(c[3])
        : "r"(a[0]), "r"(a[1]), "r"(a[2]), "r"(a[3]), "r"(b[0]), "r"(b[1]));
}

#define CP_ASYNC16(sm, gm) asm volatile("cp.async.cg.shared.global [%0], [%1], 16;" :: "r"(sm), "l"(gm))
#define CP_COMMIT()        asm volatile("cp.async.commit_group;" ::: "memory")
#define CP_WAIT(n)         asm volatile("cp.async.wait_group %0;" :: "n"(n) : "memory")

// ===========================================================================
// LayerNorm + gate logits + res_coef; emits attn as fp16
// ===========================================================================
__global__ void ln_gate_kernel(const float* __restrict__ x,
                               const float* __restrict__ nw,
                               const float* __restrict__ nb,
                               const float* __restrict__ wg,
                               const float* __restrict__ res_coef) {
    __shared__ float row[HID];
    __shared__ float rs[10], rq[10];
    __shared__ float dots[10];
    __shared__ float s_mean, s_rstd;

    const int s = blockIdx.x;
    const int tid = threadIdx.x;
    const int lane = tid & 31;
    const int w = tid >> 5;

    const float* xr = x + (size_t)s * HID;
    float sum = 0.f, sq = 0.f;
    for (int i = tid; i < HID; i += 320) {
        float v = xr[i];
        row[i] = v;
        sum += v; sq += v * v;
    }
    #pragma unroll
    for (int o = 16; o > 0; o >>= 1) {
        sum += __shfl_down_sync(0xffffffffu, sum, o);
        sq  += __shfl_down_sync(0xffffffffu, sq,  o);
    }
    if (lane == 0) { rs[w] = sum; rq[w] = sq; }
    __syncthreads();
    if (tid == 0) {
        float ts = 0.f, tq = 0.f;
        #pragma unroll
        for (int i = 0; i < 10; i++) { ts += rs[i]; tq += rq[i]; }
        float mean = ts * (1.f / HID);
        float var  = tq * (1.f / HID) - mean * mean;
        s_mean = mean;
        s_rstd = rsqrtf(var + 1e-12f);
    }
    __syncthreads();
    const float mean = s_mean, rstd = s_rstd;
    for (int i = tid; i < HID; i += 320) {
        float v = (row[i] - mean) * rstd * nw[i] + nb[i];
        row[i] = v;
        g_attn[(size_t)s * HID + i] = __float2half_rn(v);
    }
    __syncthreads();

    float d = 0.f;
    if (w < 8) {
        for (int m = lane; m < HID; m += 32) d += row[m] * wg[m * NE + w];
    } else {
        int c = w - 8;
        for (int m = lane; m < HID; m += 32) d += row[m] * res_coef[m * 2 + c];
    }
    #pragma unroll
    for (int o = 16; o > 0; o >>= 1) d += __shfl_down_sync(0xffffffffu, d, o);
    if (lane == 0) dots[w] = d;
    __syncthreads();

    if (tid == 0) {
        float mx = dots[0]; int am = 0;
        #pragma unroll
        for (int e = 1; e < 8; e++) if (dots[e] > mx) { mx = dots[e]; am = e; }
        float se = 0.f;
        #pragma unroll
        for (int e = 0; e < 8; e++) se += expf(dots[e] - mx);
        g_expidx[s] = am;
        g_gate[s] = 1.f / se;
        float a = dots[8], b = dots[9];
        float m2 = fmaxf(a, b);
        float ea = expf(a - m2), eb = expf(b - m2);
        float inv = 1.f / (ea + eb);
        g_coef0[s] = ea * inv;
        g_coef1[s] = eb * inv;
    }
}

// ===========================================================================
__global__ void scan_kernel() {
    const int tid = threadIdx.x;
    for (int i = tid; i < NE * CAP; i += 256) g_tos[i] = -1;
    __syncthreads();
    const int lane = tid & 31;
    const int e = tid >> 5;
    int count = 0;
    for (int base = 0; base < S_TOK; base += 32) {
        int s = base + lane;
        bool sel = (g_expidx[s] == e);
        unsigned mask = __ballot_sync(0xffffffffu, sel);
        if (sel) {
            int c = count + __popc(mask & ((1u << lane) - 1u));
            if (c < CAP) {
                g_dest[s] = e * CAP + c;
                g_tos[e * CAP + c] = s;
            } else {
                g_dest[s] = -1;
            }
        }
        count += __popc(mask);
    }
}

// ===========================================================================
__global__ void dispatch_kernel() {
    const int slot = blockIdx.x;
    const int tid = threadIdx.x;
    const int t = g_tos[slot];
    uint4* dst = (uint4*)(g_disp + (size_t)slot * HID);
    if (t >= 0) {
        dst[tid] = ((const uint4*)(g_attn + (size_t)t * HID))[tid];
    } else {
        dst[tid] = make_uint4(0u, 0u, 0u, 0u);
    }
}

// ===========================================================================
// Fast weight transpose + fp16 convert: W [K,N] fp32 -> T [N,K] fp16
// 64x64 tiles, 256 threads, float4 loads, 16B fp16 stores.
// ===========================================================================
__global__ __launch_bounds__(256) void wconv_kernel(const float* __restrict__ W,
                                                    __half* __restrict__ T,
                                                    int K, int N) {
    __shared__ float tile[64][65];
    const int n0 = blockIdx.x * 64;
    const int k0 = blockIdx.y * 64;
    const long zb = blockIdx.z;
    W += zb * (long)K * N;
    T += zb * (long)K * N;
    const int t = threadIdx.x;
    const int lr = t >> 4;          // 0..15
    const int lc = (t & 15) * 4;    // 0,4,..60
    #pragma unroll
    for (int i = 0; i < 4; i++) {
        int r = lr + i * 16;
        float4 v = *(const float4*)(W + (size_t)(k0 + r) * N + n0 + lc);
        tile[r][lc] = v.x; tile[r][lc + 1] = v.y;
        tile[r][lc + 2] = v.z; tile[r][lc + 3] = v.w;
    }
    __syncthreads();
    const int on = t >> 3;          // 0..31
    const int ok = (t & 7) * 8;     // 0,8,..56
    #pragma unroll
    for (int i = 0; i < 2; i++) {
        int n = on + i * 32;
        __half h[8];
        #pragma unroll
        for (int j = 0; j < 8; j++) h[j] = __float2half_rn(tile[ok + j][n]);
        *(uint4*)(T + (size_t)(n0 + n) * K + k0 + ok) = *(uint4*)h;
    }
}

// ===========================================================================
// mma.sync fp16 GEMM: C = epilogue(A @ B^T + bias)
// A: [M,K] K-major fp16. B: [N,K] K-major fp16.
// BM=BN=128, BK=64, 256 threads (8 warps, 2m x 4n), warp tile 64x32.
// 4-stage cp.async pipeline, xor swizzle (128B rows).
// ACT=0: fp32 out. ACT=1: gelu -> fp16 out.
// ACT=2: fused final combine: out = x + c0*(acc+bias) + c1*gate*eo[dest]
// ===========================================================================
template <int ACT>
__global__ __launch_bounds__(256, 1)
void mma_gemm(const __half* __restrict__ A, const __half* __restrict__ B,
              const float* __restrict__ bias,
              float* __restrict__ Cf, __half* __restrict__ Ch,
              const float* __restrict__ Xres, const float* __restrict__ Eo,
              int M, int N, int K) {
    extern __shared__ char smem[];
    const uint32_t sbase = smem_u32(smem);
    const int tid = threadIdx.x;
    const int lane = tid & 31;
    const int wid = tid >> 5;
    const int wm = wid >> 2;          // 0..1 -> warp row (64 rows each)
    const int wn = wid & 3;           // 0..3 -> warp col (32 cols each)
    const long bz = blockIdx.z;
    const int m0 = blockIdx.y * BM;
    const int n0 = blockIdx.x * BN;

    const __half* srcs[2] = {
        A + bz * (long)M * K + (size_t)m0 * K,
        B + bz * (long)N * K + (size_t)n0 * K
    };
    bias += bz * (long)N;

    const int lrow0 = tid >> 3;        // rows tid/8 + 32*i
    const int lch   = tid & 7;         // 16B chunk within 128B row

    float acc[4][4][4];
    #pragma unroll
    for (int a = 0; a < 4; a++)
        #pragma unroll
        for (int b = 0; b < 4; b++)
            #pragma unroll
            for (int c = 0; c < 4; c++) acc[a][b][c] = 0.f;

    const int NT = K / BK;

    auto load_stage = [&](int st, int kt) {
        const uint32_t stb = sbase + (uint32_t)st * STAGE_BYTES;
        #pragma unroll
        for (int t = 0; t < 2; t++) {
            const __half* g = srcs[t] + kt + lch * 8;
            const uint32_t tb = stb + (uint32_t)t * TILE_BYTES;
            #pragma unroll
            for (int i = 0; i < 4; i++) {
                int row = lrow0 + i * 32;
                uint32_t sm = tb + (uint32_t)(row * 128 + ((lch ^ (row & 7)) << 4));
                CP_ASYNC16(sm, g + (size_t)row * K);
            }
        }
    };

    // prime NSTAGE-1 stages
    #pragma unroll
    for (int p = 0; p < NSTAGE - 1; p++) {
        if (p < NT) { load_stage(p, p * BK); CP_COMMIT(); }
    }

    for (int s = 0; s < NT; s++) {
        if (s + NSTAGE - 1 < NT) CP_WAIT(NSTAGE - 2);
        else if (s + NSTAGE - 2 < NT) CP_WAIT(NSTAGE - 3);
        else if (s + NSTAGE - 3 < NT) CP_WAIT(NSTAGE - 4);
        else CP_WAIT(0);
        __syncthreads();

        if (s + NSTAGE - 1 < NT) {
            load_stage((s + NSTAGE - 1) % NSTAGE, (s + NSTAGE - 1) * BK);
            CP_COMMIT();
        }

        const uint32_t stb = sbase + (uint32_t)(s % NSTAGE) * STAGE_BYTES;
        const uint32_t Ab = stb, Bb = stb + TILE_BYTES;

        const int g = lane >> 3;       // ldmatrix address group
        const int li = lane & 7;

        #pragma unroll
        for (int kk = 0; kk < 4; kk++) {
            uint32_t af[4][4];
            {
                const int arow_b = wm * 64 + (g & 1) * 8 + li;
                const int ach = kk * 2 + (g >> 1);
                #pragma unroll
                for (int mf = 0; mf < 4; mf++) {
                    int r = arow_b + mf * 16;
                    uint32_t off = (uint32_t)(r * 128 + ((ach ^ (r & 7)) << 4));
                    ldsm_x4(af[mf], Ab + off);
                }
            }
            uint32_t bf[4][2];
            {
                const int brow_b = wn * 32 + (g >> 1) * 8 + li;
                const int bch = kk * 2 + (g & 1);
                #pragma unroll
                for (int nb = 0; nb < 2; nb++) {
                    int r = brow_b + nb * 16;
                    uint32_t off = (uint32_t)(r * 128 + ((bch ^ (r & 7)) << 4));
                    uint32_t t4[4];
                    ldsm_x4(t4, Bb + off);
                    bf[nb * 2][0] = t4[0]; bf[nb * 2][1] = t4[1];
                    bf[nb * 2 + 1][0] = t4[2]; bf[nb * 2 + 1][1] = t4[3];
                }
            }
            #pragma unroll
            for (int mf = 0; mf < 4; mf++)
                #pragma unroll
                for (int nf = 0; nf < 4; nf++)
                    mma16816(acc[mf][nf], af[mf], bf[nf]);
        }
        __syncthreads();
    }

    // ---- epilogue ----
    const int mrow = m0 + wm * 64 + (lane >> 2);
    const int ncol0 = n0 + wn * 32 + (lane & 3) * 2;
    #pragma unroll
    for (int nf = 0; nf < 4; nf++) {
        const int n = ncol0 + nf * 8;
        const float bv0 = bias[n], bv1 = bias[n + 1];
        #pragma unroll
        for (int mf = 0; mf < 4; mf++) {
            const float* c = acc[mf][nf];
            const int m_a = mrow + mf * 16;
            const int m_b = m_a + 8;
            if (ACT == 1) {
                float v00 = gelu_tanh(c[0] + bv0), v01 = gelu_tanh(c[1] + bv1);
                float v10 = gelu_tanh(c[2] + bv0), v11 = gelu_tanh(c[3] + bv1);
                uint32_t p0 = (uint32_t)__half_as_ushort(__float2half_rn(v00)) |
                              ((uint32_t)__half_as_ushort(__float2half_rn(v01)) << 16);
                uint32_t p1 = (uint32_t)__half_as_ushort(__float2half_rn(v10)) |
                              ((uint32_t)__half_as_ushort(__float2half_rn(v11)) << 16);
                *(uint32_t*)(Ch + bz * (long)M * N + (size_t)m_a * N + n) = p0;
                *(uint32_t*)(Ch + bz * (long)M * N + (size_t)m_b * N + n) = p1;
            } else if (ACT == 0) {
                float2 r0 = make_float2(c[0] + bv0, c[1] + bv1);
                float2 r1 = make_float2(c[2] + bv0, c[3] + bv1);
                *(float2*)(Cf + bz * (long)M * N + (size_t)m_a * N + n) = r0;
                *(float2*)(Cf + bz * (long)M * N + (size_t)m_b * N + n) = r1;
            } else {
                // fused combine (res GEMM2): per-row scalars
                #pragma unroll
                for (int h = 0; h < 2; h++) {
                    const int m = h ? m_b : m_a;
                    const float va = h ? (c[2] + bv0) : (c[0] + bv0);
                    const float vb = h ? (c[3] + bv1) : (c[1] + bv1);
                    const int dd = g_dest[m];
                    const float c0 = g_coef0[m];
                    const float c1g = g_coef1[m] * g_gate[m];
                    float2 xv = *(const float2*)(Xres + (size_t)m * N + n);
                    float2 ev = make_float2(0.f, 0.f);
                    if (dd >= 0) ev = *(const float2*)(Eo + (size_t)dd * N + n);
                    float2 o;
                    o.x = xv.x + c0 * va + c1g * ev.x;
                    o.y = xv.y + c0 * vb + c1g * ev.y;
                    *(float2*)(Cf + (size_t)m * N + n) = o;
                }
            }
        }
    }
}

// ===========================================================================
extern "C" void kernel_launch(void* const* d_in, const int* in_sizes, int n_in,
                              void* d_out, int out_size) {
    const float* x       = (const float*)d_in[0];
    const float* attn_nw = (const float*)d_in[1];
    const float* attn_nb = (const float*)d_in[2];
    const float* wg      = (const float*)d_in[3];
    const float* inter_w = (const float*)d_in[4];
    const float* inter_b = (const float*)d_in[5];
    const float* out_w   = (const float*)d_in[6];
    const float* out_b   = (const float*)d_in[7];
    const float* ri_w    = (const float*)d_in[8];
    const float* ri_b    = (const float*)d_in[9];
    const float* ro_w    = (const float*)d_in[10];
    const float* ro_b    = (const float*)d_in[11];
    const float* rcoef   = (const float*)d_in[12];
    float* out = (float*)d_out;

    cudaFuncSetAttribute(mma_gemm<0>, cudaFuncAttributeMaxDynamicSharedMemorySize, SMEM_BYTES);
    cudaFuncSetAttribute(mma_gemm<1>, cudaFuncAttributeMaxDynamicSharedMemorySize, SMEM_BYTES);
    cudaFuncSetAttribute(mma_gemm<2>, cudaFuncAttributeMaxDynamicSharedMemorySize, SMEM_BYTES);

    void *p_disp, *p_h, *p_eo, *p_attn, *p_rh;
    void *p_iwT, *p_owT, *p_riT, *p_roT;
    cudaGetSymbolAddress(&p_disp, g_disp);
    cudaGetSymbolAddress(&p_h, g_h);
    cudaGetSymbolAddress(&p_eo, g_eo);
    cudaGetSymbolAddress(&p_attn, g_attn);
    cudaGetSymbolAddress(&p_rh, g_rh);
    cudaGetSymbolAddress(&p_iwT, g_iwT);
    cudaGetSymbolAddress(&p_owT, g_owT);
    cudaGetSymbolAddress(&p_riT, g_riT);
    cudaGetSymbolAddress(&p_roT, g_roT);

    // weight transpose + fp16 convert (64x64 tiles)
    wconv_kernel<<<dim3(INTR / 64, HID / 64, NE), 256>>>(inter_w, (__half*)p_iwT, HID, INTR);
    wconv_kernel<<<dim3(HID / 64, INTR / 64, NE), 256>>>(out_w, (__half*)p_owT, INTR, HID);
    wconv_kernel<<<dim3(INTR / 64, HID / 64, 1), 256>>>(ri_w, (__half*)p_riT, HID, INTR);
    wconv_kernel<<<dim3(HID / 64, INTR / 64, 1), 256>>>(ro_w, (__half*)p_roT, INTR, HID);

    ln_gate_kernel<<<S_TOK, 320>>>(x, attn_nw, attn_nb, wg, rcoef);
    scan_kernel<<<1, 256>>>();
    dispatch_kernel<<<NE * CAP, 128>>>();

    // expert GEMM1 + GELU: [1024,1024]@[1024,4096] x8 -> h (fp16)
    mma_gemm<1><<<dim3(INTR / BN, CAP / BM, NE), 256, SMEM_BYTES>>>(
        (const __half*)p_disp, (const __half*)p_iwT,
        inter_b, nullptr, (__half*)p_h, nullptr, nullptr, CAP, INTR, HID);
    // expert GEMM2: [1024,4096]@[4096,1024] x8 -> eo (fp32)
    mma_gemm<0><<<dim3(HID / BN, CAP / BM, NE), 256, SMEM_BYTES>>>(
        (const __half*)p_h, (const __half*)p_owT,
        out_b, (float*)p_eo, nullptr, nullptr, nullptr, CAP, HID, INTR);
    // res GEMM1 + GELU: [8192,1024]@[1024,4096] -> rh (fp16)
    mma_gemm<1><<<dim3(INTR / BN, S_TOK / BM, 1), 256, SMEM_BYTES>>>(
        (const __half*)p_attn, (const __half*)p_riT,
        ri_b, nullptr, (__half*)p_rh, nullptr, nullptr, S_TOK, INTR, HID);
    // res GEMM2 + fused combine: out = x + c0*(rh@roT+b) + c1*gate*eo[dest]
    mma_gemm<2><<<dim3(HID / BN, S_TOK / BM, 1), 256, SMEM_BYTES>>>(
        (const __half*)p_rh, (const __half*)p_roT,
        ro_b, out, nullptr, x, (const float*)p_eo, S_TOK, HID, INTR);
}